// round 1
// baseline (speedup 1.0000x reference)
#include <cuda_runtime.h>

#define VN 100000
#define EN 1600000
#define BATCH 4
#define BN_EPS 1e-5f

// ---------------- static device scratch (no allocations allowed) ----------------
__device__ __align__(256) float g_XN[VN * 32 * BATCH];   // BN'ed input, (V,32,B)
__device__ __align__(256) float g_X0[VN * 64 * BATCH];   // hidden layer input, (V,64,B)
__device__ __align__(256) float g_SA[VN * 64 * BATCH];   // x1
__device__ __align__(256) float g_SB[VN * 64 * BATCH];   // x2
__device__ __align__(256) float g_SC[VN * 64 * BATCH];   // x3
__device__ __align__(256) float g_H [VN * 64 * BATCH];   // layer output (pre-relu)
__device__ float g_red[128];     // per-channel sum / sumsq
__device__ float g_scale[64];
__device__ float g_shift[64];

// ---------------- small utility kernels ----------------
__global__ void k_zero_red() {
    if (threadIdx.x < 128) g_red[threadIdx.x] = 0.f;
}

__global__ void k_zero(float4* __restrict__ y, int n4) {
    int i = blockIdx.x * 256 + threadIdx.x;
    if (i < n4) y[i] = make_float4(0.f, 0.f, 0.f, 0.f);
}

__global__ void k_negcopy(float4* __restrict__ y, const float4* __restrict__ x, int n4) {
    int i = blockIdx.x * 256 + threadIdx.x;
    if (i < n4) {
        float4 v = x[i];
        y[i] = make_float4(-v.x, -v.y, -v.z, -v.w);
    }
}

// ---------------- BN stats on raw input x, layout (B, C, V) ----------------
__global__ void k_stats_in(const float* __restrict__ x, int C) {
    int c = blockIdx.y;
    float s1 = 0.f, s2 = 0.f;
    for (int v = blockIdx.x * blockDim.x + threadIdx.x; v < VN; v += gridDim.x * blockDim.x) {
#pragma unroll
        for (int b = 0; b < BATCH; b++) {
            float t = x[(b * C + c) * VN + v];
            s1 += t; s2 += t * t;
        }
    }
    __shared__ float sh1[256], sh2[256];
    sh1[threadIdx.x] = s1; sh2[threadIdx.x] = s2;
    __syncthreads();
    for (int off = 128; off > 0; off >>= 1) {
        if (threadIdx.x < off) {
            sh1[threadIdx.x] += sh1[threadIdx.x + off];
            sh2[threadIdx.x] += sh2[threadIdx.x + off];
        }
        __syncthreads();
    }
    if (threadIdx.x == 0) {
        atomicAdd(&g_red[c], sh1[0]);
        atomicAdd(&g_red[64 + c], sh2[0]);
    }
}

// ---------------- BN finalize: scale/shift from sums, then re-zero g_red ----------------
__global__ void k_finalize(const float* __restrict__ gam, const float* __restrict__ bet, int C) {
    int c = threadIdx.x;  // 128 threads
    float sc = 0.f, sf = 0.f;
    if (c < C) {
        float n = (float)VN * (float)BATCH;
        float m = g_red[c] / n;
        float var = g_red[64 + c] / n - m * m;
        sc = gam[c] * rsqrtf(var + BN_EPS);
        sf = bet[c] - m * sc;
    }
    __syncthreads();
    if (c < C) { g_scale[c] = sc; g_shift[c] = sf; }
    g_red[c] = 0.f;
}

// ---------------- apply input BN with transpose (B,C,V) -> (V,C,B) ----------------
__global__ void k_apply_in(const float* __restrict__ x, float4* __restrict__ xn) {
    int idx = blockIdx.x * 256 + threadIdx.x;  // over 32*V, c-major
    if (idx >= 32 * VN) return;
    int c = idx / VN, v = idx - c * VN;
    float sc = g_scale[c], sf = g_shift[c];
    float4 r;
    r.x = sc * x[(0 * 32 + c) * VN + v] + sf;
    r.y = sc * x[(1 * 32 + c) * VN + v] + sf;
    r.z = sc * x[(2 * 32 + c) * VN + v] + sf;
    r.w = sc * x[(3 * 32 + c) * VN + v] + sf;
    xn[v * 32 + c] = r;
}

// ---------------- BN stats on hidden H, layout (V,C,B) as float4, relu fused ----------------
__global__ void k_stats_h(const float4* __restrict__ H, int C) {
    int tid = threadIdx.x;
    int gsz = gridDim.x * 256;
    int g = blockIdx.x * 256 + tid;
    int c = g % C;
    float s1 = 0.f, s2 = 0.f;
    for (int v = g / C; v < VN; v += gsz / C) {
        float4 h = H[v * C + c];
        float a = fmaxf(h.x, 0.f), b = fmaxf(h.y, 0.f);
        float d = fmaxf(h.z, 0.f), e = fmaxf(h.w, 0.f);
        s1 += a + b + d + e;
        s2 += a * a + b * b + d * d + e * e;
    }
    __shared__ float sh1[256], sh2[256];
    sh1[tid] = s1; sh2[tid] = s2;
    __syncthreads();
    for (int off = 128; off >= C; off >>= 1) {
        if (tid < off) { sh1[tid] += sh1[tid + off]; sh2[tid] += sh2[tid + off]; }
        __syncthreads();
    }
    if (tid < C) {
        atomicAdd(&g_red[tid], sh1[tid]);
        atomicAdd(&g_red[64 + tid], sh2[tid]);
    }
}

// ---------------- apply hidden BN + relu, (V,C,B) -> (V,C,B) ----------------
__global__ void k_apply_h(const float4* __restrict__ H, float4* __restrict__ Xo, int C) {
    int g = blockIdx.x * 256 + threadIdx.x;
    if (g >= VN * 64) return;   // C is always 64 here; keep generic bound via arg
    if (g >= VN * C) return;
    int c = g % C;
    float sc = g_scale[c], sf = g_shift[c];
    float4 h = H[g];
    float4 r;
    r.x = sc * fmaxf(h.x, 0.f) + sf;
    r.y = sc * fmaxf(h.y, 0.f) + sf;
    r.z = sc * fmaxf(h.z, 0.f) + sf;
    r.w = sc * fmaxf(h.w, 0.f) + sf;
    Xo[g] = r;
}

// ---------------- scatter SpMM: Y[r] += coef*vals[e]*X[c], vectorized red.v4 ----------------
template<int CBV4>  // float4s per vertex: 32 (C=32) or 64 (C=64)
__global__ void k_scatter(const int* __restrict__ rows, const int* __restrict__ cols,
                          const float* __restrict__ vals, float coef,
                          const float4* __restrict__ X, float* __restrict__ Y) {
    int t = blockIdx.x * 256 + threadIdx.x;
    int e = t / CBV4;
    if (e >= EN) return;
    int j = t - e * CBV4;
    int r = rows[e];
    int c = cols[e];
    float wv = coef * vals[e];
    float4 x = X[c * CBV4 + j];
    float* dst = Y + (r * CBV4 + j) * 4;
    asm volatile("red.global.add.v4.f32 [%0], {%1, %2, %3, %4};"
                 :: "l"(dst), "f"(wv * x.x), "f"(wv * x.y), "f"(wv * x.z), "f"(wv * x.w)
                 : "memory");
}

// ---------------- combine: out[v,o,b] = bias[o] + sum_k sum_c w[k,c,o]*xk[v,c,b] ----------------
template<int C, int O, bool LAST>
__global__ void k_combine(const float4* __restrict__ x0, const float4* __restrict__ x1,
                          const float4* __restrict__ x2, const float4* __restrict__ x3,
                          const float* __restrict__ w, const float* __restrict__ bias,
                          float4* __restrict__ outH, float* __restrict__ outF,
                          const float4* __restrict__ xn) {
    const int KC = 4 * C;
    const int VPB = 256 / O;
    extern __shared__ char smem[];
    float* sW = (float*)smem;
    float4* sX = (float4*)(smem + (size_t)KC * O * sizeof(float));
    const int tid = threadIdx.x;

    for (int i = tid; i < KC * O; i += 256) sW[i] = w[i];

    const int v0 = blockIdx.x * VPB;
    for (int i = tid; i < VPB * KC; i += 256) {
        int vs = i / KC, kc = i - vs * KC;
        int k = kc / C, cc = kc - k * C;
        int v = v0 + vs;
        const float4* src = (k == 0) ? x0 : (k == 1) ? x1 : (k == 2) ? x2 : x3;
        sX[i] = (v < VN) ? src[v * C + cc] : make_float4(0.f, 0.f, 0.f, 0.f);
    }
    __syncthreads();

    int o = tid % O;
    int vs = tid / O;
    int v = v0 + vs;
    if (v >= VN) return;

    float bb = bias[o];
    float4 acc = make_float4(bb, bb, bb, bb);
    const float4* xv = sX + vs * KC;
#pragma unroll 8
    for (int kc = 0; kc < KC; kc++) {
        float wv = sW[kc * O + o];
        float4 xx = xv[kc];
        acc.x += wv * xx.x; acc.y += wv * xx.y;
        acc.z += wv * xx.z; acc.w += wv * xx.w;
    }

    if (!LAST) {
        outH[v * O + o] = acc;
    } else {
        float4 r = xn[v * O + o];  // O == 32 == input channels
        outF[(0 * O + o) * VN + v] = fmaxf(acc.x + r.x, 0.f);
        outF[(1 * O + o) * VN + v] = fmaxf(acc.y + r.y, 0.f);
        outF[(2 * O + o) * VN + v] = fmaxf(acc.z + r.z, 0.f);
        outF[(3 * O + o) * VN + v] = fmaxf(acc.w + r.w, 0.f);
    }
}

// ---------------- host orchestration ----------------
extern "C" void kernel_launch(void* const* d_in, const int* in_sizes, int n_in,
                              void* d_out, int out_size) {
    const float* x       = (const float*)d_in[0];
    const int*   ei      = (const int*)  d_in[1];
    const float* vals    = (const float*)d_in[2];
    const float* in_bn_g = (const float*)d_in[3];
    const float* in_bn_b = (const float*)d_in[4];
    const float* in_w    = (const float*)d_in[5];
    const float* in_b    = (const float*)d_in[6];
    const float* h0_bn_g = (const float*)d_in[7];
    const float* h0_bn_b = (const float*)d_in[8];
    const float* h0_w    = (const float*)d_in[9];
    const float* h0_b    = (const float*)d_in[10];
    const float* h1_bn_g = (const float*)d_in[11];
    const float* h1_bn_b = (const float*)d_in[12];
    const float* h1_w    = (const float*)d_in[13];
    const float* h1_b    = (const float*)d_in[14];
    float* out = (float*)d_out;

    const int* rows = ei;
    const int* cols = ei + EN;

    void *pXN, *pX0, *pSA, *pSB, *pSC, *pH;
    cudaGetSymbolAddress(&pXN, g_XN);
    cudaGetSymbolAddress(&pX0, g_X0);
    cudaGetSymbolAddress(&pSA, g_SA);
    cudaGetSymbolAddress(&pSB, g_SB);
    cudaGetSymbolAddress(&pSC, g_SC);
    cudaGetSymbolAddress(&pH,  g_H);
    float4* XN = (float4*)pXN;
    float4* X0 = (float4*)pX0;
    float4* SA = (float4*)pSA;
    float4* SB = (float4*)pSB;
    float4* SC = (float4*)pSC;
    float4* H  = (float4*)pH;

    // opt-in shared memory for the big combine kernels
    cudaFuncSetAttribute(k_combine<32, 64, false>, cudaFuncAttributeMaxDynamicSharedMemorySize, 40960);
    cudaFuncSetAttribute(k_combine<64, 64, false>, cudaFuncAttributeMaxDynamicSharedMemorySize, 81920);
    cudaFuncSetAttribute(k_combine<64, 32, true>,  cudaFuncAttributeMaxDynamicSharedMemorySize, 65536);

    const int n4_32 = VN * 32;   // float4 count for C=32 buffers
    const int n4_64 = VN * 64;   // float4 count for C=64 buffers
    const int gz32 = (n4_32 + 255) / 256;
    const int gz64 = (n4_64 + 255) / 256;
    const int gsc32 = (EN * 32) / 256;   // scatter grid, CBV4=32
    const int gsc64 = (EN * 64) / 256;   // scatter grid, CBV4=64

    // ---- input BN ----
    k_zero_red<<<1, 128>>>();
    k_stats_in<<<dim3(64, 32), 256>>>(x, 32);
    k_finalize<<<1, 128>>>(in_bn_g, in_bn_b, 32);
    k_apply_in<<<(32 * VN + 255) / 256, 256>>>(x, XN);

    // ---- layer 0: C=32 -> O=64, X0 = XN ----
    k_zero<<<gz32, 256>>>(SA, n4_32);
    k_scatter<32><<<gsc32, 256>>>(rows, cols, vals, 1.f, XN, (float*)SA);
    k_negcopy<<<gz32, 256>>>(SB, XN, n4_32);
    k_scatter<32><<<gsc32, 256>>>(rows, cols, vals, 2.f, SA, (float*)SB);
    k_negcopy<<<gz32, 256>>>(SC, SA, n4_32);
    k_scatter<32><<<gsc32, 256>>>(rows, cols, vals, 2.f, SB, (float*)SC);
    k_combine<32, 64, false><<<(VN + 3) / 4, 256, 40960>>>(XN, SA, SB, SC, in_w, in_b, H, nullptr, nullptr);

    // ---- BN + relu on hidden 0 ----
    k_stats_h<<<512, 256>>>(H, 64);
    k_finalize<<<1, 128>>>(h0_bn_g, h0_bn_b, 64);
    k_apply_h<<<gz64, 256>>>(H, X0, 64);

    // ---- layer 1: C=64 -> O=64 ----
    k_zero<<<gz64, 256>>>(SA, n4_64);
    k_scatter<64><<<gsc64, 256>>>(rows, cols, vals, 1.f, X0, (float*)SA);
    k_negcopy<<<gz64, 256>>>(SB, X0, n4_64);
    k_scatter<64><<<gsc64, 256>>>(rows, cols, vals, 2.f, SA, (float*)SB);
    k_negcopy<<<gz64, 256>>>(SC, SA, n4_64);
    k_scatter<64><<<gsc64, 256>>>(rows, cols, vals, 2.f, SB, (float*)SC);
    k_combine<64, 64, false><<<(VN + 3) / 4, 256, 81920>>>(X0, SA, SB, SC, h0_w, h0_b, H, nullptr, nullptr);

    // ---- BN + relu on hidden 1 ----
    k_stats_h<<<512, 256>>>(H, 64);
    k_finalize<<<1, 128>>>(h1_bn_g, h1_bn_b, 64);
    k_apply_h<<<gz64, 256>>>(H, X0, 64);

    // ---- layer 2: C=64 -> O=32, fused residual + relu + transpose to (B,O,V) ----
    k_zero<<<gz64, 256>>>(SA, n4_64);
    k_scatter<64><<<gsc64, 256>>>(rows, cols, vals, 1.f, X0, (float*)SA);
    k_negcopy<<<gz64, 256>>>(SB, X0, n4_64);
    k_scatter<64><<<gsc64, 256>>>(rows, cols, vals, 2.f, SA, (float*)SB);
    k_negcopy<<<gz64, 256>>>(SC, SA, n4_64);
    k_scatter<64><<<gsc64, 256>>>(rows, cols, vals, 2.f, SB, (float*)SC);
    k_combine<64, 32, true><<<(VN + 7) / 8, 256, 65536>>>(X0, SA, SB, SC, h1_w, h1_b, nullptr, out, XN);
}

// round 2
// speedup vs baseline: 1.8824x; 1.8824x over previous
#include <cuda_runtime.h>

#define VN 100000
#define EN 1600000
#define BATCH 4
#define BN_EPS 1e-5f
#define NB_SCAN 98   // ceil(VN/1024)

// ---------------- static device scratch (no allocations allowed) ----------------
__device__ __align__(256) float g_XN[VN * 32 * BATCH];   // BN'ed input, (V,32,B)
__device__ __align__(256) float g_X0[VN * 64 * BATCH];   // hidden layer input, (V,64,B)
__device__ __align__(256) float g_SA[VN * 64 * BATCH];   // x1
__device__ __align__(256) float g_SB[VN * 64 * BATCH];   // x2
__device__ __align__(256) float g_SC[VN * 64 * BATCH];   // x3
__device__ __align__(256) float g_H [VN * 64 * BATCH];   // layer output (pre-relu)
__device__ float g_red[128];     // per-channel sum / sumsq
__device__ float g_scale[64];
__device__ float g_shift[64];

// CSR scratch
__device__ __align__(256) int   g_deg[VN];
__device__ __align__(256) int   g_rowptr[VN + 1];
__device__ __align__(256) int   g_cursor[VN];
__device__ __align__(256) int   g_ecol[EN];
__device__ __align__(256) float g_eval[EN];
__device__ int g_bsum[128];
__device__ int g_boff[128];

// ---------------- CSR build ----------------
__global__ void k_deg_zero() {
    int i = blockIdx.x * 256 + threadIdx.x;
    if (i < VN) g_deg[i] = 0;
    if (i < 128) g_red[i] = 0.f;   // also zero BN accumulators
}

__global__ void k_hist(const int* __restrict__ rows) {
    int e = blockIdx.x * 256 + threadIdx.x;
    if (e < EN) atomicAdd(&g_deg[rows[e]], 1);
}

__global__ void k_bsum() {
    __shared__ int sh[1024];
    int i = blockIdx.x * 1024 + threadIdx.x;
    sh[threadIdx.x] = (i < VN) ? g_deg[i] : 0;
    __syncthreads();
    for (int off = 512; off > 0; off >>= 1) {
        if (threadIdx.x < off) sh[threadIdx.x] += sh[threadIdx.x + off];
        __syncthreads();
    }
    if (threadIdx.x == 0) g_bsum[blockIdx.x] = sh[0];
}

__global__ void k_bscan() {
    __shared__ int sh[128];
    int t = threadIdx.x;
    int v = (t < NB_SCAN) ? g_bsum[t] : 0;
    sh[t] = v;
    __syncthreads();
    for (int off = 1; off < 128; off <<= 1) {
        int tmp = (t >= off) ? sh[t - off] : 0;
        __syncthreads();
        sh[t] += tmp;
        __syncthreads();
    }
    g_boff[t] = sh[t] - v;   // exclusive
    if (t == 0) g_rowptr[VN] = EN;
}

__global__ void k_scan_final() {
    __shared__ int sh[1024];
    int t = threadIdx.x;
    int i = blockIdx.x * 1024 + t;
    int v = (i < VN) ? g_deg[i] : 0;
    sh[t] = v;
    __syncthreads();
    for (int off = 1; off < 1024; off <<= 1) {
        int tmp = (t >= off) ? sh[t - off] : 0;
        __syncthreads();
        sh[t] += tmp;
        __syncthreads();
    }
    if (i < VN) {
        int excl = g_boff[blockIdx.x] + sh[t] - v;
        g_rowptr[i] = excl;
        g_cursor[i] = excl;
    }
}

__global__ void k_fill(const int* __restrict__ rows, const int* __restrict__ cols,
                       const float* __restrict__ vals) {
    int e = blockIdx.x * 256 + threadIdx.x;
    if (e < EN) {
        int r = rows[e];
        int pos = atomicAdd(&g_cursor[r], 1);
        g_ecol[pos] = cols[e];
        g_eval[pos] = vals[e];
    }
}

// ---------------- BN stats on raw input x, layout (B, C, V) ----------------
__global__ void k_stats_in(const float* __restrict__ x, int C) {
    int c = blockIdx.y;
    float s1 = 0.f, s2 = 0.f;
    for (int v = blockIdx.x * blockDim.x + threadIdx.x; v < VN; v += gridDim.x * blockDim.x) {
#pragma unroll
        for (int b = 0; b < BATCH; b++) {
            float t = x[(b * C + c) * VN + v];
            s1 += t; s2 += t * t;
        }
    }
    __shared__ float sh1[256], sh2[256];
    sh1[threadIdx.x] = s1; sh2[threadIdx.x] = s2;
    __syncthreads();
    for (int off = 128; off > 0; off >>= 1) {
        if (threadIdx.x < off) {
            sh1[threadIdx.x] += sh1[threadIdx.x + off];
            sh2[threadIdx.x] += sh2[threadIdx.x + off];
        }
        __syncthreads();
    }
    if (threadIdx.x == 0) {
        atomicAdd(&g_red[c], sh1[0]);
        atomicAdd(&g_red[64 + c], sh2[0]);
    }
}

// ---------------- BN finalize ----------------
__global__ void k_finalize(const float* __restrict__ gam, const float* __restrict__ bet, int C) {
    int c = threadIdx.x;  // 128 threads
    float sc = 0.f, sf = 0.f;
    if (c < C) {
        float n = (float)VN * (float)BATCH;
        float m = g_red[c] / n;
        float var = g_red[64 + c] / n - m * m;
        sc = gam[c] * rsqrtf(var + BN_EPS);
        sf = bet[c] - m * sc;
    }
    __syncthreads();
    if (c < C) { g_scale[c] = sc; g_shift[c] = sf; }
    g_red[c] = 0.f;
}

// ---------------- apply input BN with tiled transpose (B,C,V) -> (V,C,B) ----------------
__global__ void k_apply_in(const float* __restrict__ x, float4* __restrict__ xn) {
    __shared__ float4 tile[64 * 33];   // padded: stride 33 avoids bank conflicts
    int v0 = blockIdx.x * 64;
    for (int i = threadIdx.x; i < 32 * 64; i += 256) {
        int c = i >> 6, vi = i & 63;
        int v = v0 + vi;
        float4 r = make_float4(0.f, 0.f, 0.f, 0.f);
        if (v < VN) {
            float sc = g_scale[c], sf = g_shift[c];
            r.x = sc * x[(0 * 32 + c) * VN + v] + sf;
            r.y = sc * x[(1 * 32 + c) * VN + v] + sf;
            r.z = sc * x[(2 * 32 + c) * VN + v] + sf;
            r.w = sc * x[(3 * 32 + c) * VN + v] + sf;
        }
        tile[vi * 33 + c] = r;
    }
    __syncthreads();
    for (int i = threadIdx.x; i < 32 * 64; i += 256) {
        int vi = i >> 5, c = i & 31;
        int v = v0 + vi;
        if (v < VN) xn[v * 32 + c] = tile[vi * 33 + c];
    }
}

// ---------------- BN stats on hidden H, layout (V,C,B) as float4, relu fused ----------------
__global__ void k_stats_h(const float4* __restrict__ H, int C) {
    int tid = threadIdx.x;
    int gsz = gridDim.x * 256;
    int g = blockIdx.x * 256 + tid;
    int c = g % C;
    float s1 = 0.f, s2 = 0.f;
    for (int v = g / C; v < VN; v += gsz / C) {
        float4 h = H[v * C + c];
        float a = fmaxf(h.x, 0.f), b = fmaxf(h.y, 0.f);
        float d = fmaxf(h.z, 0.f), e = fmaxf(h.w, 0.f);
        s1 += a + b + d + e;
        s2 += a * a + b * b + d * d + e * e;
    }
    __shared__ float sh1[256], sh2[256];
    sh1[tid] = s1; sh2[tid] = s2;
    __syncthreads();
    for (int off = 128; off >= C; off >>= 1) {
        if (tid < off) { sh1[tid] += sh1[tid + off]; sh2[tid] += sh2[tid + off]; }
        __syncthreads();
    }
    if (tid < C) {
        atomicAdd(&g_red[tid], sh1[tid]);
        atomicAdd(&g_red[64 + tid], sh2[tid]);
    }
}

// ---------------- apply hidden BN + relu ----------------
__global__ void k_apply_h(const float4* __restrict__ H, float4* __restrict__ Xo, int C) {
    int g = blockIdx.x * 256 + threadIdx.x;
    if (g >= VN * C) return;
    int c = g % C;
    float sc = g_scale[c], sf = g_shift[c];
    float4 h = H[g];
    float4 r;
    r.x = sc * fmaxf(h.x, 0.f) + sf;
    r.y = sc * fmaxf(h.y, 0.f) + sf;
    r.z = sc * fmaxf(h.z, 0.f) + sf;
    r.w = sc * fmaxf(h.w, 0.f) + sf;
    Xo[g] = r;
}

// ---------------- gather SpMM: Y[v] = coef * sum_e val[e]*X[col[e]]  (- Z[v] if Z) ----------------
template<int F4>   // float4s per vertex row: 32 (C=32) or 64 (C=64)
__global__ void k_gather(float coef, const float4* __restrict__ X,
                         const float4* __restrict__ Z, float4* __restrict__ Y) {
    const int G = 256 / F4;
    int tid = threadIdx.x;
    int v = blockIdx.x * G + tid / F4;
    int j = tid & (F4 - 1);
    if (v >= VN) return;
    int s = g_rowptr[v];
    int e = g_rowptr[v + 1];
    float4 acc = make_float4(0.f, 0.f, 0.f, 0.f);
    int i = s;
    for (; i + 4 <= e; i += 4) {
        int   c0 = g_ecol[i],     c1 = g_ecol[i + 1], c2 = g_ecol[i + 2], c3 = g_ecol[i + 3];
        float w0 = g_eval[i],     w1 = g_eval[i + 1], w2 = g_eval[i + 2], w3 = g_eval[i + 3];
        float4 x0 = X[c0 * F4 + j];
        float4 x1 = X[c1 * F4 + j];
        float4 x2 = X[c2 * F4 + j];
        float4 x3 = X[c3 * F4 + j];
        acc.x += w0 * x0.x + w1 * x1.x + w2 * x2.x + w3 * x3.x;
        acc.y += w0 * x0.y + w1 * x1.y + w2 * x2.y + w3 * x3.y;
        acc.z += w0 * x0.z + w1 * x1.z + w2 * x2.z + w3 * x3.z;
        acc.w += w0 * x0.w + w1 * x1.w + w2 * x2.w + w3 * x3.w;
    }
    for (; i < e; i++) {
        int c = g_ecol[i];
        float w = g_eval[i];
        float4 x = X[c * F4 + j];
        acc.x += w * x.x; acc.y += w * x.y; acc.z += w * x.z; acc.w += w * x.w;
    }
    float4 r;
    if (Z != nullptr) {
        float4 z = Z[v * F4 + j];
        r = make_float4(coef * acc.x - z.x, coef * acc.y - z.y,
                        coef * acc.z - z.z, coef * acc.w - z.w);
    } else {
        r = make_float4(coef * acc.x, coef * acc.y, coef * acc.z, coef * acc.w);
    }
    Y[v * F4 + j] = r;
}

// ---------------- combine: out[v,o,b] = bias[o] + sum_k sum_c w[k,c,o]*xk[v,c,b] ----------------
template<int C, int O, bool LAST>
__global__ void k_combine(const float4* __restrict__ x0, const float4* __restrict__ x1,
                          const float4* __restrict__ x2, const float4* __restrict__ x3,
                          const float* __restrict__ w, const float* __restrict__ bias,
                          float4* __restrict__ outH, float* __restrict__ outF,
                          const float4* __restrict__ xn) {
    const int KC = 4 * C;
    const int VPB = 256 / O;
    extern __shared__ char smem[];
    float* sW = (float*)smem;
    float4* sX = (float4*)(smem + (size_t)KC * O * sizeof(float));
    const int tid = threadIdx.x;

    for (int i = tid; i < KC * O; i += 256) sW[i] = w[i];

    const int v0 = blockIdx.x * VPB;
    for (int i = tid; i < VPB * KC; i += 256) {
        int vs = i / KC, kc = i - vs * KC;
        int k = kc / C, cc = kc - k * C;
        int v = v0 + vs;
        const float4* src = (k == 0) ? x0 : (k == 1) ? x1 : (k == 2) ? x2 : x3;
        sX[i] = (v < VN) ? src[v * C + cc] : make_float4(0.f, 0.f, 0.f, 0.f);
    }
    __syncthreads();

    int o = tid % O;
    int vs = tid / O;
    int v = v0 + vs;
    if (v >= VN) return;

    float bb = bias[o];
    float4 acc = make_float4(bb, bb, bb, bb);
    const float4* xv = sX + vs * KC;
#pragma unroll 8
    for (int kc = 0; kc < KC; kc++) {
        float wv = sW[kc * O + o];
        float4 xx = xv[kc];
        acc.x += wv * xx.x; acc.y += wv * xx.y;
        acc.z += wv * xx.z; acc.w += wv * xx.w;
    }

    if (!LAST) {
        outH[v * O + o] = acc;
    } else {
        float4 r = xn[v * O + o];  // O == 32 == input channels
        outF[(0 * O + o) * VN + v] = fmaxf(acc.x + r.x, 0.f);
        outF[(1 * O + o) * VN + v] = fmaxf(acc.y + r.y, 0.f);
        outF[(2 * O + o) * VN + v] = fmaxf(acc.z + r.z, 0.f);
        outF[(3 * O + o) * VN + v] = fmaxf(acc.w + r.w, 0.f);
    }
}

// ---------------- host orchestration ----------------
extern "C" void kernel_launch(void* const* d_in, const int* in_sizes, int n_in,
                              void* d_out, int out_size) {
    const float* x       = (const float*)d_in[0];
    const int*   ei      = (const int*)  d_in[1];
    const float* vals    = (const float*)d_in[2];
    const float* in_bn_g = (const float*)d_in[3];
    const float* in_bn_b = (const float*)d_in[4];
    const float* in_w    = (const float*)d_in[5];
    const float* in_b    = (const float*)d_in[6];
    const float* h0_bn_g = (const float*)d_in[7];
    const float* h0_bn_b = (const float*)d_in[8];
    const float* h0_w    = (const float*)d_in[9];
    const float* h0_b    = (const float*)d_in[10];
    const float* h1_bn_g = (const float*)d_in[11];
    const float* h1_bn_b = (const float*)d_in[12];
    const float* h1_w    = (const float*)d_in[13];
    const float* h1_b    = (const float*)d_in[14];
    float* out = (float*)d_out;

    const int* rows = ei;
    const int* cols = ei + EN;

    void *pXN, *pX0, *pSA, *pSB, *pSC, *pH;
    cudaGetSymbolAddress(&pXN, g_XN);
    cudaGetSymbolAddress(&pX0, g_X0);
    cudaGetSymbolAddress(&pSA, g_SA);
    cudaGetSymbolAddress(&pSB, g_SB);
    cudaGetSymbolAddress(&pSC, g_SC);
    cudaGetSymbolAddress(&pH,  g_H);
    float4* XN = (float4*)pXN;
    float4* X0 = (float4*)pX0;
    float4* SA = (float4*)pSA;
    float4* SB = (float4*)pSB;
    float4* SC = (float4*)pSC;
    float4* H  = (float4*)pH;

    cudaFuncSetAttribute(k_combine<32, 64, false>, cudaFuncAttributeMaxDynamicSharedMemorySize, 40960);
    cudaFuncSetAttribute(k_combine<64, 64, false>, cudaFuncAttributeMaxDynamicSharedMemorySize, 81920);
    cudaFuncSetAttribute(k_combine<64, 32, true>,  cudaFuncAttributeMaxDynamicSharedMemorySize, 65536);

    const int gz64 = (VN * 64 + 255) / 256;
    const int gE   = (EN + 255) / 256;
    const int gG32 = (VN + 7) / 8;    // gather grid, F4=32
    const int gG64 = (VN + 3) / 4;    // gather grid, F4=64

    // ---- CSR build (every launch; deterministic enough for fp tolerance) ----
    k_deg_zero<<<(VN + 255) / 256, 256>>>();
    k_hist<<<gE, 256>>>(rows);
    k_bsum<<<NB_SCAN, 1024>>>();
    k_bscan<<<1, 128>>>();
    k_scan_final<<<NB_SCAN, 1024>>>();
    k_fill<<<gE, 256>>>(rows, cols, vals);

    // ---- input BN ----
    k_stats_in<<<dim3(64, 32), 256>>>(x, 32);
    k_finalize<<<1, 128>>>(in_bn_g, in_bn_b, 32);
    k_apply_in<<<(VN + 63) / 64, 256>>>(x, XN);

    // ---- layer 0: C=32 -> O=64 ----
    k_gather<32><<<gG32, 256>>>(1.f, XN, nullptr, SA);      // x1 = L @ x0
    k_gather<32><<<gG32, 256>>>(2.f, SA, XN, SB);           // x2 = 2 L x1 - x0
    k_gather<32><<<gG32, 256>>>(2.f, SB, SA, SC);           // x3 = 2 L x2 - x1
    k_combine<32, 64, false><<<(VN + 3) / 4, 256, 40960>>>(XN, SA, SB, SC, in_w, in_b, H, nullptr, nullptr);

    // ---- BN + relu on hidden 0 ----
    k_stats_h<<<512, 256>>>(H, 64);
    k_finalize<<<1, 128>>>(h0_bn_g, h0_bn_b, 64);
    k_apply_h<<<gz64, 256>>>(H, X0, 64);

    // ---- layer 1: C=64 -> O=64 ----
    k_gather<64><<<gG64, 256>>>(1.f, X0, nullptr, SA);
    k_gather<64><<<gG64, 256>>>(2.f, SA, X0, SB);
    k_gather<64><<<gG64, 256>>>(2.f, SB, SA, SC);
    k_combine<64, 64, false><<<(VN + 3) / 4, 256, 81920>>>(X0, SA, SB, SC, h0_w, h0_b, H, nullptr, nullptr);

    // ---- BN + relu on hidden 1 ----
    k_stats_h<<<512, 256>>>(H, 64);
    k_finalize<<<1, 128>>>(h1_bn_g, h1_bn_b, 64);
    k_apply_h<<<gz64, 256>>>(H, X0, 64);

    // ---- layer 2: C=64 -> O=32, fused residual + relu + transpose to (B,O,V) ----
    k_gather<64><<<gG64, 256>>>(1.f, X0, nullptr, SA);
    k_gather<64><<<gG64, 256>>>(2.f, SA, X0, SB);
    k_gather<64><<<gG64, 256>>>(2.f, SB, SA, SC);
    k_combine<64, 32, true><<<(VN + 7) / 8, 256, 65536>>>(X0, SA, SB, SC, h1_w, h1_b, nullptr, out, XN);
}

// round 3
// speedup vs baseline: 1.8975x; 1.0080x over previous
#include <cuda_runtime.h>

#define VN 100000
#define EN 1600000
#define BATCH 4
#define BN_EPS 1e-5f
#define NB_SCAN 98   // ceil(VN/1024)

// ---------------- static device scratch (no allocations allowed) ----------------
__device__ __align__(256) float g_XN[VN * 32 * BATCH];   // BN'ed input, (V,32,B)
__device__ __align__(256) float g_X0[VN * 64 * BATCH];   // hidden layer input, (V,64,B)
__device__ __align__(256) float g_SA[VN * 64 * BATCH];   // x1
__device__ __align__(256) float g_SB[VN * 64 * BATCH];   // x2
__device__ __align__(256) float g_SC[VN * 64 * BATCH];   // x3
__device__ __align__(256) float g_H [VN * 64 * BATCH];   // layer output (pre-relu)
__device__ float g_red[128];     // per-channel sum / sumsq
__device__ float g_scale[64];
__device__ float g_shift[64];

// CSR scratch
__device__ __align__(256) int   g_deg[VN];
__device__ __align__(256) int   g_rowptr[VN + 1];
__device__ __align__(256) int   g_cursor[VN];
__device__ __align__(256) int   g_ecol[EN];
__device__ __align__(256) float g_eval[EN];
__device__ int g_bsum[128];
__device__ int g_boff[128];

// ---------------- CSR build ----------------
__global__ void k_deg_zero() {
    int i = blockIdx.x * 256 + threadIdx.x;
    if (i < VN) g_deg[i] = 0;
    if (i < 128) g_red[i] = 0.f;   // also zero BN accumulators
}

__global__ void k_hist(const int* __restrict__ rows) {
    int e = blockIdx.x * 256 + threadIdx.x;
    if (e < EN) atomicAdd(&g_deg[rows[e]], 1);
}

__global__ void k_bsum() {
    __shared__ int sh[1024];
    int i = blockIdx.x * 1024 + threadIdx.x;
    sh[threadIdx.x] = (i < VN) ? g_deg[i] : 0;
    __syncthreads();
    for (int off = 512; off > 0; off >>= 1) {
        if (threadIdx.x < off) sh[threadIdx.x] += sh[threadIdx.x + off];
        __syncthreads();
    }
    if (threadIdx.x == 0) g_bsum[blockIdx.x] = sh[0];
}

__global__ void k_bscan() {
    __shared__ int sh[128];
    int t = threadIdx.x;
    int v = (t < NB_SCAN) ? g_bsum[t] : 0;
    sh[t] = v;
    __syncthreads();
    for (int off = 1; off < 128; off <<= 1) {
        int tmp = (t >= off) ? sh[t - off] : 0;
        __syncthreads();
        sh[t] += tmp;
        __syncthreads();
    }
    g_boff[t] = sh[t] - v;   // exclusive
    if (t == 0) g_rowptr[VN] = EN;
}

__global__ void k_scan_final() {
    __shared__ int sh[1024];
    int t = threadIdx.x;
    int i = blockIdx.x * 1024 + t;
    int v = (i < VN) ? g_deg[i] : 0;
    sh[t] = v;
    __syncthreads();
    for (int off = 1; off < 1024; off <<= 1) {
        int tmp = (t >= off) ? sh[t - off] : 0;
        __syncthreads();
        sh[t] += tmp;
        __syncthreads();
    }
    if (i < VN) {
        int excl = g_boff[blockIdx.x] + sh[t] - v;
        g_rowptr[i] = excl;
        g_cursor[i] = excl;
    }
}

__global__ void k_fill(const int* __restrict__ rows, const int* __restrict__ cols,
                       const float* __restrict__ vals) {
    int e = blockIdx.x * 256 + threadIdx.x;
    if (e < EN) {
        int r = rows[e];
        int pos = atomicAdd(&g_cursor[r], 1);
        g_ecol[pos] = cols[e];
        g_eval[pos] = vals[e];
    }
}

// ---------------- BN stats on raw input x, layout (B, C, V) ----------------
__global__ void k_stats_in(const float* __restrict__ x, int C) {
    int c = blockIdx.y;
    float s1 = 0.f, s2 = 0.f;
    for (int v = blockIdx.x * blockDim.x + threadIdx.x; v < VN; v += gridDim.x * blockDim.x) {
#pragma unroll
        for (int b = 0; b < BATCH; b++) {
            float t = x[(b * C + c) * VN + v];
            s1 += t; s2 += t * t;
        }
    }
    __shared__ float sh1[256], sh2[256];
    sh1[threadIdx.x] = s1; sh2[threadIdx.x] = s2;
    __syncthreads();
    for (int off = 128; off > 0; off >>= 1) {
        if (threadIdx.x < off) {
            sh1[threadIdx.x] += sh1[threadIdx.x + off];
            sh2[threadIdx.x] += sh2[threadIdx.x + off];
        }
        __syncthreads();
    }
    if (threadIdx.x == 0) {
        atomicAdd(&g_red[c], sh1[0]);
        atomicAdd(&g_red[64 + c], sh2[0]);
    }
}

// ---------------- BN finalize ----------------
__global__ void k_finalize(const float* __restrict__ gam, const float* __restrict__ bet, int C) {
    int c = threadIdx.x;  // 128 threads
    float sc = 0.f, sf = 0.f;
    if (c < C) {
        float n = (float)VN * (float)BATCH;
        float m = g_red[c] / n;
        float var = g_red[64 + c] / n - m * m;
        sc = gam[c] * rsqrtf(var + BN_EPS);
        sf = bet[c] - m * sc;
    }
    __syncthreads();
    if (c < C) { g_scale[c] = sc; g_shift[c] = sf; }
    g_red[c] = 0.f;
}

// ---------------- apply input BN with tiled transpose (B,C,V) -> (V,C,B) ----------------
__global__ void k_apply_in(const float* __restrict__ x, float4* __restrict__ xn) {
    __shared__ float4 tile[64 * 33];   // padded: stride 33 avoids bank conflicts
    int v0 = blockIdx.x * 64;
    for (int i = threadIdx.x; i < 32 * 64; i += 256) {
        int c = i >> 6, vi = i & 63;
        int v = v0 + vi;
        float4 r = make_float4(0.f, 0.f, 0.f, 0.f);
        if (v < VN) {
            float sc = g_scale[c], sf = g_shift[c];
            r.x = sc * x[(0 * 32 + c) * VN + v] + sf;
            r.y = sc * x[(1 * 32 + c) * VN + v] + sf;
            r.z = sc * x[(2 * 32 + c) * VN + v] + sf;
            r.w = sc * x[(3 * 32 + c) * VN + v] + sf;
        }
        tile[vi * 33 + c] = r;
    }
    __syncthreads();
    for (int i = threadIdx.x; i < 32 * 64; i += 256) {
        int vi = i >> 5, c = i & 31;
        int v = v0 + vi;
        if (v < VN) xn[v * 32 + c] = tile[vi * 33 + c];
    }
}

// ---------------- apply hidden BN + relu ----------------
__global__ void k_apply_h(const float4* __restrict__ H, float4* __restrict__ Xo, int C) {
    int g = blockIdx.x * 256 + threadIdx.x;
    if (g >= VN * C) return;
    int c = g % C;
    float sc = g_scale[c], sf = g_shift[c];
    float4 h = H[g];
    float4 r;
    r.x = sc * fmaxf(h.x, 0.f) + sf;
    r.y = sc * fmaxf(h.y, 0.f) + sf;
    r.z = sc * fmaxf(h.z, 0.f) + sf;
    r.w = sc * fmaxf(h.w, 0.f) + sf;
    Xo[g] = r;
}

// ---------------- gather SpMM, warp-per-vertex, 32 float4 slice per pass ----------------
// Y[v, off+j] = coef * sum_e val[e] * X[col[e], off+j]   (- Z[v, off+j] if Z)
template<int ROWF4>   // float4 row stride: 32 (C=32) or 64 (C=64)
__global__ void __launch_bounds__(256) k_gather(float coef, const float4* __restrict__ X,
                                                const float4* __restrict__ Z,
                                                float4* __restrict__ Y, int off) {
    int v = blockIdx.x * 8 + (threadIdx.x >> 5);
    int j = (threadIdx.x & 31) + off;
    if (v >= VN) return;
    int s = g_rowptr[v];
    int e = g_rowptr[v + 1];
    float4 acc = make_float4(0.f, 0.f, 0.f, 0.f);
    int i = s;
    // align edge index to 4 for vector metadata loads
    for (; i < e && (i & 3); i++) {
        int   c = __ldcs(&g_ecol[i]);
        float w = __ldcs(&g_eval[i]);
        float4 x = X[c * ROWF4 + j];
        acc.x += w * x.x; acc.y += w * x.y; acc.z += w * x.z; acc.w += w * x.w;
    }
    for (; i + 4 <= e; i += 4) {
        int4   cc = __ldcs((const int4*)&g_ecol[i]);
        float4 ww = __ldcs((const float4*)&g_eval[i]);
        float4 x0 = X[cc.x * ROWF4 + j];
        float4 x1 = X[cc.y * ROWF4 + j];
        float4 x2 = X[cc.z * ROWF4 + j];
        float4 x3 = X[cc.w * ROWF4 + j];
        acc.x += ww.x * x0.x + ww.y * x1.x + ww.z * x2.x + ww.w * x3.x;
        acc.y += ww.x * x0.y + ww.y * x1.y + ww.z * x2.y + ww.w * x3.y;
        acc.z += ww.x * x0.z + ww.y * x1.z + ww.z * x2.z + ww.w * x3.z;
        acc.w += ww.x * x0.w + ww.y * x1.w + ww.z * x2.w + ww.w * x3.w;
    }
    for (; i < e; i++) {
        int   c = __ldcs(&g_ecol[i]);
        float w = __ldcs(&g_eval[i]);
        float4 x = X[c * ROWF4 + j];
        acc.x += w * x.x; acc.y += w * x.y; acc.z += w * x.z; acc.w += w * x.w;
    }
    float4 r;
    if (Z != nullptr) {
        float4 z = __ldcs(&Z[v * ROWF4 + j]);
        r = make_float4(coef * acc.x - z.x, coef * acc.y - z.y,
                        coef * acc.z - z.z, coef * acc.w - z.w);
    } else {
        r = make_float4(coef * acc.x, coef * acc.y, coef * acc.z, coef * acc.w);
    }
    __stcs(&Y[v * ROWF4 + j], r);
}

// ---------------- combine: out[v,o,b] = bias[o] + sum_k sum_c w[k,c,o]*xk[v,c,b] ----------------
// For !LAST, also accumulates BN stats of relu(out) into g_red (fused k_stats_h).
template<int C, int O, bool LAST>
__global__ void __launch_bounds__(256) k_combine(
        const float4* __restrict__ x0, const float4* __restrict__ x1,
        const float4* __restrict__ x2, const float4* __restrict__ x3,
        const float* __restrict__ w, const float* __restrict__ bias,
        float4* __restrict__ outH, float* __restrict__ outF,
        const float4* __restrict__ xn) {
    const int KC = 4 * C;
    const int VPB = 256 / O;
    extern __shared__ char smem[];
    float* sW = (float*)smem;
    float4* sX = (float4*)(smem + (size_t)KC * O * sizeof(float));
    __shared__ float sS1[64], sS2[64];
    const int tid = threadIdx.x;

    if (!LAST && tid < O) { sS1[tid] = 0.f; sS2[tid] = 0.f; }

    for (int i = tid; i < KC * O; i += 256) sW[i] = w[i];

    const int v0 = blockIdx.x * VPB;
    for (int i = tid; i < VPB * KC; i += 256) {
        int vs = i / KC, kc = i - vs * KC;
        int k = kc / C, cc = kc - k * C;
        int v = v0 + vs;
        const float4* src = (k == 0) ? x0 : (k == 1) ? x1 : (k == 2) ? x2 : x3;
        sX[i] = (v < VN) ? src[v * C + cc] : make_float4(0.f, 0.f, 0.f, 0.f);
    }
    __syncthreads();

    int o = tid % O;
    int vs = tid / O;
    int v = v0 + vs;

    if (v < VN) {
        float bb = bias[o];
        float4 acc = make_float4(bb, bb, bb, bb);
        const float4* xv = sX + vs * KC;
#pragma unroll 8
        for (int kc = 0; kc < KC; kc++) {
            float wv = sW[kc * O + o];
            float4 xx = xv[kc];
            acc.x += wv * xx.x; acc.y += wv * xx.y;
            acc.z += wv * xx.z; acc.w += wv * xx.w;
        }

        if (!LAST) {
            outH[v * O + o] = acc;
            // fused BN stats on relu(acc)
            float a = fmaxf(acc.x, 0.f), b = fmaxf(acc.y, 0.f);
            float d = fmaxf(acc.z, 0.f), f = fmaxf(acc.w, 0.f);
            atomicAdd(&sS1[o], a + b + d + f);
            atomicAdd(&sS2[o], a * a + b * b + d * d + f * f);
        } else {
            float4 r = xn[v * O + o];  // O == 32 == input channels
            outF[(0 * O + o) * VN + v] = fmaxf(acc.x + r.x, 0.f);
            outF[(1 * O + o) * VN + v] = fmaxf(acc.y + r.y, 0.f);
            outF[(2 * O + o) * VN + v] = fmaxf(acc.z + r.z, 0.f);
            outF[(3 * O + o) * VN + v] = fmaxf(acc.w + r.w, 0.f);
        }
    }

    if (!LAST) {
        __syncthreads();
        if (tid < O) {
            atomicAdd(&g_red[tid], sS1[tid]);
            atomicAdd(&g_red[64 + tid], sS2[tid]);
        }
    }
}

// ---------------- host orchestration ----------------
extern "C" void kernel_launch(void* const* d_in, const int* in_sizes, int n_in,
                              void* d_out, int out_size) {
    const float* x       = (const float*)d_in[0];
    const int*   ei      = (const int*)  d_in[1];
    const float* vals    = (const float*)d_in[2];
    const float* in_bn_g = (const float*)d_in[3];
    const float* in_bn_b = (const float*)d_in[4];
    const float* in_w    = (const float*)d_in[5];
    const float* in_b    = (const float*)d_in[6];
    const float* h0_bn_g = (const float*)d_in[7];
    const float* h0_bn_b = (const float*)d_in[8];
    const float* h0_w    = (const float*)d_in[9];
    const float* h0_b    = (const float*)d_in[10];
    const float* h1_bn_g = (const float*)d_in[11];
    const float* h1_bn_b = (const float*)d_in[12];
    const float* h1_w    = (const float*)d_in[13];
    const float* h1_b    = (const float*)d_in[14];
    float* out = (float*)d_out;

    const int* rows = ei;
    const int* cols = ei + EN;

    void *pXN, *pX0, *pSA, *pSB, *pSC, *pH;
    cudaGetSymbolAddress(&pXN, g_XN);
    cudaGetSymbolAddress(&pX0, g_X0);
    cudaGetSymbolAddress(&pSA, g_SA);
    cudaGetSymbolAddress(&pSB, g_SB);
    cudaGetSymbolAddress(&pSC, g_SC);
    cudaGetSymbolAddress(&pH,  g_H);
    float4* XN = (float4*)pXN;
    float4* X0 = (float4*)pX0;
    float4* SA = (float4*)pSA;
    float4* SB = (float4*)pSB;
    float4* SC = (float4*)pSC;
    float4* H  = (float4*)pH;

    cudaFuncSetAttribute(k_combine<32, 64, false>, cudaFuncAttributeMaxDynamicSharedMemorySize, 40960);
    cudaFuncSetAttribute(k_combine<64, 64, false>, cudaFuncAttributeMaxDynamicSharedMemorySize, 81920);
    cudaFuncSetAttribute(k_combine<64, 32, true>,  cudaFuncAttributeMaxDynamicSharedMemorySize, 65536);

    const int gz64 = (VN * 64 + 255) / 256;
    const int gE   = (EN + 255) / 256;
    const int gG   = (VN + 7) / 8;    // warp-per-vertex gather grid

    // ---- CSR build (every launch; deterministic enough for fp tolerance) ----
    k_deg_zero<<<(VN + 255) / 256, 256>>>();
    k_hist<<<gE, 256>>>(rows);
    k_bsum<<<NB_SCAN, 1024>>>();
    k_bscan<<<1, 128>>>();
    k_scan_final<<<NB_SCAN, 1024>>>();
    k_fill<<<gE, 256>>>(rows, cols, vals);

    // ---- input BN ----
    k_stats_in<<<dim3(64, 32), 256>>>(x, 32);
    k_finalize<<<1, 128>>>(in_bn_g, in_bn_b, 32);
    k_apply_in<<<(VN + 63) / 64, 256>>>(x, XN);

    // ---- layer 0: C=32 -> O=64 (X = 51MB, fits L2 in one pass) ----
    k_gather<32><<<gG, 256>>>(1.f, XN, nullptr, SA, 0);     // x1 = L x0
    k_gather<32><<<gG, 256>>>(2.f, SA, XN, SB, 0);          // x2 = 2 L x1 - x0
    k_gather<32><<<gG, 256>>>(2.f, SB, SA, SC, 0);          // x3 = 2 L x2 - x1
    k_combine<32, 64, false><<<(VN + 3) / 4, 256, 40960>>>(XN, SA, SB, SC, in_w, in_b, H, nullptr, nullptr);

    // ---- BN + relu on hidden 0 (stats fused into combine) ----
    k_finalize<<<1, 128>>>(h0_bn_g, h0_bn_b, 64);
    k_apply_h<<<gz64, 256>>>(H, X0, 64);

    // ---- layer 1: C=64 -> O=64, channel-split gathers (51MB per pass) ----
    k_gather<64><<<gG, 256>>>(1.f, X0, nullptr, SA, 0);
    k_gather<64><<<gG, 256>>>(1.f, X0, nullptr, SA, 32);
    k_gather<64><<<gG, 256>>>(2.f, SA, X0, SB, 0);
    k_gather<64><<<gG, 256>>>(2.f, SA, X0, SB, 32);
    k_gather<64><<<gG, 256>>>(2.f, SB, SA, SC, 0);
    k_gather<64><<<gG, 256>>>(2.f, SB, SA, SC, 32);
    k_combine<64, 64, false><<<(VN + 3) / 4, 256, 81920>>>(X0, SA, SB, SC, h0_w, h0_b, H, nullptr, nullptr);

    // ---- BN + relu on hidden 1 (stats fused into combine) ----
    k_finalize<<<1, 128>>>(h1_bn_g, h1_bn_b, 64);
    k_apply_h<<<gz64, 256>>>(H, X0, 64);

    // ---- layer 2: C=64 -> O=32, channel-split gathers, fused residual+relu+transpose ----
    k_gather<64><<<gG, 256>>>(1.f, X0, nullptr, SA, 0);
    k_gather<64><<<gG, 256>>>(1.f, X0, nullptr, SA, 32);
    k_gather<64><<<gG, 256>>>(2.f, SA, X0, SB, 0);
    k_gather<64><<<gG, 256>>>(2.f, SA, X0, SB, 32);
    k_gather<64><<<gG, 256>>>(2.f, SB, SA, SC, 0);
    k_gather<64><<<gG, 256>>>(2.f, SB, SA, SC, 32);
    k_combine<64, 32, true><<<(VN + 7) / 8, 256, 65536>>>(X0, SA, SB, SC, h1_w, h1_b, nullptr, out, XN);
}

// round 4
// speedup vs baseline: 2.3256x; 1.2256x over previous
#include <cuda_runtime.h>

#define VN 100000
#define EN 1600000
#define BATCH 4
#define BN_EPS 1e-5f
#define NB_SCAN 98   // ceil(VN/1024)

// ---------------- static device scratch (no allocations allowed) ----------------
__device__ __align__(256) float g_XN[VN * 32 * BATCH];   // BN'ed input, (V,32,B)
__device__ __align__(256) float g_X0[VN * 64 * BATCH];   // hidden layer input / b2
__device__ __align__(256) float g_SA[VN * 64 * BATCH];   // x1 / y0
__device__ __align__(256) float g_SB[VN * 64 * BATCH];   // x2 / y1
__device__ __align__(256) float g_SC[VN * 64 * BATCH];   // x3 / y2 / b1
__device__ __align__(256) float g_H [VN * 64 * BATCH];   // layer output (pre-relu) / y3
__device__ float g_red[128];     // per-channel sum / sumsq
__device__ float g_scale[64];
__device__ float g_shift[64];

// CSR scratch
__device__ __align__(256) int   g_deg[VN];
__device__ __align__(256) int   g_rowptr[VN + 1];
__device__ __align__(256) int   g_cursor[VN];
__device__ __align__(256) int   g_ecol[EN];
__device__ __align__(256) float g_eval[EN];
__device__ int g_bsum[128];
__device__ int g_boff[128];

// ---------------- CSR build ----------------
__global__ void k_deg_zero() {
    int i = blockIdx.x * 256 + threadIdx.x;
    if (i < VN) g_deg[i] = 0;
    if (i < 128) g_red[i] = 0.f;   // also zero BN accumulators
}

__global__ void k_hist(const int* __restrict__ rows) {
    int e = blockIdx.x * 256 + threadIdx.x;
    if (e < EN) atomicAdd(&g_deg[rows[e]], 1);
}

__global__ void k_bsum() {
    __shared__ int sh[1024];
    int i = blockIdx.x * 1024 + threadIdx.x;
    sh[threadIdx.x] = (i < VN) ? g_deg[i] : 0;
    __syncthreads();
    for (int off = 512; off > 0; off >>= 1) {
        if (threadIdx.x < off) sh[threadIdx.x] += sh[threadIdx.x + off];
        __syncthreads();
    }
    if (threadIdx.x == 0) g_bsum[blockIdx.x] = sh[0];
}

__global__ void k_bscan() {
    __shared__ int sh[128];
    int t = threadIdx.x;
    int v = (t < NB_SCAN) ? g_bsum[t] : 0;
    sh[t] = v;
    __syncthreads();
    for (int off = 1; off < 128; off <<= 1) {
        int tmp = (t >= off) ? sh[t - off] : 0;
        __syncthreads();
        sh[t] += tmp;
        __syncthreads();
    }
    g_boff[t] = sh[t] - v;   // exclusive
    if (t == 0) g_rowptr[VN] = EN;
}

__global__ void k_scan_final() {
    __shared__ int sh[1024];
    int t = threadIdx.x;
    int i = blockIdx.x * 1024 + t;
    int v = (i < VN) ? g_deg[i] : 0;
    sh[t] = v;
    __syncthreads();
    for (int off = 1; off < 1024; off <<= 1) {
        int tmp = (t >= off) ? sh[t - off] : 0;
        __syncthreads();
        sh[t] += tmp;
        __syncthreads();
    }
    if (i < VN) {
        int excl = g_boff[blockIdx.x] + sh[t] - v;
        g_rowptr[i] = excl;
        g_cursor[i] = excl;
    }
}

__global__ void k_fill(const int* __restrict__ rows, const int* __restrict__ cols,
                       const float* __restrict__ vals) {
    int e = blockIdx.x * 256 + threadIdx.x;
    if (e < EN) {
        int r = rows[e];
        int pos = atomicAdd(&g_cursor[r], 1);
        g_ecol[pos] = cols[e];
        g_eval[pos] = vals[e];
    }
}

// ---------------- BN stats on raw input x, layout (B, C, V) ----------------
__global__ void k_stats_in(const float* __restrict__ x, int C) {
    int c = blockIdx.y;
    float s1 = 0.f, s2 = 0.f;
    for (int v = blockIdx.x * blockDim.x + threadIdx.x; v < VN; v += gridDim.x * blockDim.x) {
#pragma unroll
        for (int b = 0; b < BATCH; b++) {
            float t = x[(b * C + c) * VN + v];
            s1 += t; s2 += t * t;
        }
    }
    __shared__ float sh1[256], sh2[256];
    sh1[threadIdx.x] = s1; sh2[threadIdx.x] = s2;
    __syncthreads();
    for (int off = 128; off > 0; off >>= 1) {
        if (threadIdx.x < off) {
            sh1[threadIdx.x] += sh1[threadIdx.x + off];
            sh2[threadIdx.x] += sh2[threadIdx.x + off];
        }
        __syncthreads();
    }
    if (threadIdx.x == 0) {
        atomicAdd(&g_red[c], sh1[0]);
        atomicAdd(&g_red[64 + c], sh2[0]);
    }
}

// ---------------- BN finalize ----------------
__global__ void k_finalize(const float* __restrict__ gam, const float* __restrict__ bet, int C) {
    int c = threadIdx.x;  // 128 threads
    float sc = 0.f, sf = 0.f;
    if (c < C) {
        float n = (float)VN * (float)BATCH;
        float m = g_red[c] / n;
        float var = g_red[64 + c] / n - m * m;
        sc = gam[c] * rsqrtf(var + BN_EPS);
        sf = bet[c] - m * sc;
    }
    __syncthreads();
    if (c < C) { g_scale[c] = sc; g_shift[c] = sf; }
    g_red[c] = 0.f;
}

// ---------------- apply input BN with tiled transpose (B,C,V) -> (V,C,B) ----------------
__global__ void k_apply_in(const float* __restrict__ x, float4* __restrict__ xn) {
    __shared__ float4 tile[64 * 33];
    int v0 = blockIdx.x * 64;
    for (int i = threadIdx.x; i < 32 * 64; i += 256) {
        int c = i >> 6, vi = i & 63;
        int v = v0 + vi;
        float4 r = make_float4(0.f, 0.f, 0.f, 0.f);
        if (v < VN) {
            float sc = g_scale[c], sf = g_shift[c];
            r.x = sc * x[(0 * 32 + c) * VN + v] + sf;
            r.y = sc * x[(1 * 32 + c) * VN + v] + sf;
            r.z = sc * x[(2 * 32 + c) * VN + v] + sf;
            r.w = sc * x[(3 * 32 + c) * VN + v] + sf;
        }
        tile[vi * 33 + c] = r;
    }
    __syncthreads();
    for (int i = threadIdx.x; i < 32 * 64; i += 256) {
        int vi = i >> 5, c = i & 31;
        int v = v0 + vi;
        if (v < VN) xn[v * 32 + c] = tile[vi * 33 + c];
    }
}

// ---------------- apply hidden BN + relu ----------------
__global__ void k_apply_h(const float4* __restrict__ H, float4* __restrict__ Xo, int C) {
    int g = blockIdx.x * 256 + threadIdx.x;
    if (g >= VN * C) return;
    int c = g % C;
    float sc = g_scale[c], sf = g_shift[c];
    float4 h = H[g];
    float4 r;
    r.x = sc * fmaxf(h.x, 0.f) + sf;
    r.y = sc * fmaxf(h.y, 0.f) + sf;
    r.z = sc * fmaxf(h.z, 0.f) + sf;
    r.w = sc * fmaxf(h.w, 0.f) + sf;
    Xo[g] = r;
}

// ---------------- gather SpMM, warp-per-vertex slice ----------------
// acc = sum_e val[e] * X[col[e]];  r = coef*acc + s1*Z1 + s2*Z2 (flags)
// FINAL: r += bias[c] + xn residual, relu, transposed store to (B,C,V)
template<int ROWF4, bool HASZ1, bool HASZ2, bool FINAL>
__global__ void __launch_bounds__(256) k_gather(
        float coef, const float4* __restrict__ X,
        const float4* __restrict__ Z1, float s1,
        const float4* __restrict__ Z2, float s2,
        float4* __restrict__ Y, int off,
        const float* __restrict__ bias, const float4* __restrict__ xn,
        float* __restrict__ outF) {
    __shared__ float4 tile[8 * 32];
    int wid = threadIdx.x >> 5;
    int v = blockIdx.x * 8 + wid;
    int lane = threadIdx.x & 31;
    int j = lane + off;

    float4 r = make_float4(0.f, 0.f, 0.f, 0.f);
    if (v < VN) {
        int s = g_rowptr[v];
        int e = g_rowptr[v + 1];
        float4 acc = make_float4(0.f, 0.f, 0.f, 0.f);
        int i = s;
        for (; i < e && (i & 3); i++) {
            int   c = __ldcs(&g_ecol[i]);
            float w = __ldcs(&g_eval[i]);
            float4 x = X[c * ROWF4 + j];
            acc.x += w * x.x; acc.y += w * x.y; acc.z += w * x.z; acc.w += w * x.w;
        }
        for (; i + 4 <= e; i += 4) {
            int4   cc = __ldcs((const int4*)&g_ecol[i]);
            float4 ww = __ldcs((const float4*)&g_eval[i]);
            float4 x0 = X[cc.x * ROWF4 + j];
            float4 x1 = X[cc.y * ROWF4 + j];
            float4 x2 = X[cc.z * ROWF4 + j];
            float4 x3 = X[cc.w * ROWF4 + j];
            acc.x += ww.x * x0.x + ww.y * x1.x + ww.z * x2.x + ww.w * x3.x;
            acc.y += ww.x * x0.y + ww.y * x1.y + ww.z * x2.y + ww.w * x3.y;
            acc.z += ww.x * x0.z + ww.y * x1.z + ww.z * x2.z + ww.w * x3.z;
            acc.w += ww.x * x0.w + ww.y * x1.w + ww.z * x2.w + ww.w * x3.w;
        }
        for (; i < e; i++) {
            int   c = __ldcs(&g_ecol[i]);
            float w = __ldcs(&g_eval[i]);
            float4 x = X[c * ROWF4 + j];
            acc.x += w * x.x; acc.y += w * x.y; acc.z += w * x.z; acc.w += w * x.w;
        }
        r = make_float4(coef * acc.x, coef * acc.y, coef * acc.z, coef * acc.w);
        if (HASZ1) {
            float4 z = __ldcs(&Z1[v * ROWF4 + j]);
            r.x += s1 * z.x; r.y += s1 * z.y; r.z += s1 * z.z; r.w += s1 * z.w;
        }
        if (HASZ2) {
            float4 z = __ldcs(&Z2[v * ROWF4 + j]);
            r.x += s2 * z.x; r.y += s2 * z.y; r.z += s2 * z.z; r.w += s2 * z.w;
        }
        if (!FINAL) {
            __stcs(&Y[v * ROWF4 + j], r);
        }
    }

    if (FINAL) {
        // ROWF4 == 32; add bias + residual, relu, transpose to (B,32,V)
        if (v < VN) {
            float bb = bias[j];
            float4 res = xn[v * 32 + j];
            r.x = fmaxf(r.x + bb + res.x, 0.f);
            r.y = fmaxf(r.y + bb + res.y, 0.f);
            r.z = fmaxf(r.z + bb + res.z, 0.f);
            r.w = fmaxf(r.w + bb + res.w, 0.f);
        }
        tile[wid * 32 + lane] = r;
        __syncthreads();
        int vl = threadIdx.x & 7;
        int c  = threadIdx.x >> 3;     // 0..31
        int vv = blockIdx.x * 8 + vl;
        if (vv < VN) {
            float4 t = tile[vl * 32 + c];
            outF[(0 * 32 + c) * VN + vv] = t.x;
            outF[(1 * 32 + c) * VN + vv] = t.y;
            outF[(2 * 32 + c) * VN + vv] = t.z;
            outF[(3 * 32 + c) * VN + vv] = t.w;
        }
    }
}

// ---------------- combine: H[v,o,b] = bias[o] + sum_kc w[kc,o]*xk[v,kc,b] ----------------
// Processes ITER vertex-groups per block to amortize the sW load.
// Also accumulates BN stats of relu(out) into g_red.
template<int C, int O, int ITER>
__global__ void __launch_bounds__(256) k_combine(
        const float4* __restrict__ x0, const float4* __restrict__ x1,
        const float4* __restrict__ x2, const float4* __restrict__ x3,
        const float* __restrict__ w, const float* __restrict__ bias,
        float4* __restrict__ outH) {
    const int KC = 4 * C;
    const int VPB = 256 / O;
    extern __shared__ char smem[];
    float* sW = (float*)smem;
    float4* sX = (float4*)(smem + (size_t)KC * O * sizeof(float));
    __shared__ float sS1[64], sS2[64];
    const int tid = threadIdx.x;

    if (tid < O) { sS1[tid] = 0.f; sS2[tid] = 0.f; }
    for (int i = tid; i < KC * O; i += 256) sW[i] = w[i];

    const int o = tid % O;
    const int vs = tid / O;
    const float bb = bias[o];
    float ls1 = 0.f, ls2 = 0.f;

    for (int it = 0; it < ITER; it++) {
        const int v0 = (blockIdx.x * ITER + it) * VPB;
        __syncthreads();
        for (int i = tid; i < VPB * KC; i += 256) {
            int vsl = i / KC, kc = i - vsl * KC;
            int k = kc / C, cc = kc - k * C;
            int v = v0 + vsl;
            const float4* src = (k == 0) ? x0 : (k == 1) ? x1 : (k == 2) ? x2 : x3;
            sX[i] = (v < VN) ? src[v * C + cc] : make_float4(0.f, 0.f, 0.f, 0.f);
        }
        __syncthreads();

        int v = v0 + vs;
        if (v < VN) {
            float4 acc = make_float4(bb, bb, bb, bb);
            const float4* xv = sX + vs * KC;
#pragma unroll 8
            for (int kc = 0; kc < KC; kc++) {
                float wv = sW[kc * O + o];
                float4 xx = xv[kc];
                acc.x += wv * xx.x; acc.y += wv * xx.y;
                acc.z += wv * xx.z; acc.w += wv * xx.w;
            }
            outH[v * O + o] = acc;
            float a = fmaxf(acc.x, 0.f), b = fmaxf(acc.y, 0.f);
            float d = fmaxf(acc.z, 0.f), f = fmaxf(acc.w, 0.f);
            ls1 += a + b + d + f;
            ls2 += a * a + b * b + d * d + f * f;
        }
    }

    atomicAdd(&sS1[o], ls1);
    atomicAdd(&sS2[o], ls2);
    __syncthreads();
    if (tid < O) {
        atomicAdd(&g_red[tid], sS1[tid]);
        atomicAdd(&g_red[64 + tid], sS2[tid]);
    }
}

// ---------------- combine4 (layer 2): y_k[v,o,b] = sum_c w[k,c,o]*x[v,c,b], k=0..3 ----------
template<int ITER>
__global__ void __launch_bounds__(256) k_combine4(
        const float4* __restrict__ x, const float* __restrict__ w,
        float4* __restrict__ y0, float4* __restrict__ y1,
        float4* __restrict__ y2, float4* __restrict__ y3) {
    // C=64 in, O=32 out per k; 128 outputs per vertex -> VPB=2
    __shared__ float sW[4 * 64 * 32];     // 32KB
    __shared__ float4 sX[2 * 64];         // 2KB
    const int tid = threadIdx.x;

    for (int i = tid; i < 4 * 64 * 32; i += 256) sW[i] = w[i];

    const int o2 = tid & 127;        // (k,o)
    const int k  = o2 >> 5;
    const int o  = o2 & 31;
    const int vs = tid >> 7;         // 0..1
    float4* yk = (k == 0) ? y0 : (k == 1) ? y1 : (k == 2) ? y2 : y3;
    const float* wk = sW + k * 64 * 32;

    for (int it = 0; it < ITER; it++) {
        const int v0 = (blockIdx.x * ITER + it) * 2;
        __syncthreads();
        for (int i = tid; i < 2 * 64; i += 256) {
            int vsl = i >> 6, cc = i & 63;
            int v = v0 + vsl;
            sX[i] = (v < VN) ? x[v * 64 + cc] : make_float4(0.f, 0.f, 0.f, 0.f);
        }
        __syncthreads();

        int v = v0 + vs;
        if (v < VN) {
            float4 acc = make_float4(0.f, 0.f, 0.f, 0.f);
            const float4* xv = sX + vs * 64;
#pragma unroll 8
            for (int c = 0; c < 64; c++) {
                float wv = wk[c * 32 + o];
                float4 xx = xv[c];
                acc.x += wv * xx.x; acc.y += wv * xx.y;
                acc.z += wv * xx.z; acc.w += wv * xx.w;
            }
            yk[v * 32 + o] = acc;
        }
    }
}

// ---------------- host orchestration ----------------
extern "C" void kernel_launch(void* const* d_in, const int* in_sizes, int n_in,
                              void* d_out, int out_size) {
    const float* x       = (const float*)d_in[0];
    const int*   ei      = (const int*)  d_in[1];
    const float* vals    = (const float*)d_in[2];
    const float* in_bn_g = (const float*)d_in[3];
    const float* in_bn_b = (const float*)d_in[4];
    const float* in_w    = (const float*)d_in[5];
    const float* in_b    = (const float*)d_in[6];
    const float* h0_bn_g = (const float*)d_in[7];
    const float* h0_bn_b = (const float*)d_in[8];
    const float* h0_w    = (const float*)d_in[9];
    const float* h0_b    = (const float*)d_in[10];
    const float* h1_bn_g = (const float*)d_in[11];
    const float* h1_bn_b = (const float*)d_in[12];
    const float* h1_w    = (const float*)d_in[13];
    const float* h1_b    = (const float*)d_in[14];
    float* out = (float*)d_out;

    const int* rows = ei;
    const int* cols = ei + EN;

    void *pXN, *pX0, *pSA, *pSB, *pSC, *pH;
    cudaGetSymbolAddress(&pXN, g_XN);
    cudaGetSymbolAddress(&pX0, g_X0);
    cudaGetSymbolAddress(&pSA, g_SA);
    cudaGetSymbolAddress(&pSB, g_SB);
    cudaGetSymbolAddress(&pSC, g_SC);
    cudaGetSymbolAddress(&pH,  g_H);
    float4* XN = (float4*)pXN;
    float4* X0 = (float4*)pX0;
    float4* SA = (float4*)pSA;
    float4* SB = (float4*)pSB;
    float4* SC = (float4*)pSC;
    float4* H  = (float4*)pH;

    cudaFuncSetAttribute(k_combine<32, 64, 4>, cudaFuncAttributeMaxDynamicSharedMemorySize, 40960);
    cudaFuncSetAttribute(k_combine<64, 64, 4>, cudaFuncAttributeMaxDynamicSharedMemorySize, 81920);

    const int gz64 = (VN * 64 + 255) / 256;
    const int gE   = (EN + 255) / 256;
    const int gG   = (VN + 7) / 8;         // warp-per-vertex gather grid
    const int gCMB = (VN + 15) / 16;       // combine grids (16 vertices/block)

    // ---- CSR build ----
    k_deg_zero<<<(VN + 255) / 256, 256>>>();
    k_hist<<<gE, 256>>>(rows);
    k_bsum<<<NB_SCAN, 1024>>>();
    k_bscan<<<1, 128>>>();
    k_scan_final<<<NB_SCAN, 1024>>>();
    k_fill<<<gE, 256>>>(rows, cols, vals);

    // ---- input BN ----
    k_stats_in<<<dim3(64, 32), 256>>>(x, 32);
    k_finalize<<<1, 128>>>(in_bn_g, in_bn_b, 32);
    k_apply_in<<<(VN + 63) / 64, 256>>>(x, XN);

    // ---- layer 0: C=32 -> O=64 ----
    k_gather<32, false, false, false><<<gG, 256>>>(1.f, XN, nullptr, 0.f, nullptr, 0.f, SA, 0, nullptr, nullptr, nullptr);
    k_gather<32, true,  false, false><<<gG, 256>>>(2.f, SA, XN, -1.f, nullptr, 0.f, SB, 0, nullptr, nullptr, nullptr);
    k_gather<32, true,  false, false><<<gG, 256>>>(2.f, SB, SA, -1.f, nullptr, 0.f, SC, 0, nullptr, nullptr, nullptr);
    k_combine<32, 64, 4><<<gCMB, 256, 40960>>>(XN, SA, SB, SC, in_w, in_b, H);

    // ---- BN + relu on hidden 0 (stats fused into combine) ----
    k_finalize<<<1, 128>>>(h0_bn_g, h0_bn_b, 64);
    k_apply_h<<<gz64, 256>>>(H, X0, 64);

    // ---- layer 1: C=64 -> O=64, channel-split gathers ----
    k_gather<64, false, false, false><<<gG, 256>>>(1.f, X0, nullptr, 0.f, nullptr, 0.f, SA, 0,  nullptr, nullptr, nullptr);
    k_gather<64, false, false, false><<<gG, 256>>>(1.f, X0, nullptr, 0.f, nullptr, 0.f, SA, 32, nullptr, nullptr, nullptr);
    k_gather<64, true,  false, false><<<gG, 256>>>(2.f, SA, X0, -1.f, nullptr, 0.f, SB, 0,  nullptr, nullptr, nullptr);
    k_gather<64, true,  false, false><<<gG, 256>>>(2.f, SA, X0, -1.f, nullptr, 0.f, SB, 32, nullptr, nullptr, nullptr);
    k_gather<64, true,  false, false><<<gG, 256>>>(2.f, SB, SA, -1.f, nullptr, 0.f, SC, 0,  nullptr, nullptr, nullptr);
    k_gather<64, true,  false, false><<<gG, 256>>>(2.f, SB, SA, -1.f, nullptr, 0.f, SC, 32, nullptr, nullptr, nullptr);
    k_combine<64, 64, 4><<<gCMB, 256, 81920>>>(X0, SA, SB, SC, h0_w, h0_b, H);

    // ---- BN + relu on hidden 1 (stats fused into combine) ----
    k_finalize<<<1, 128>>>(h1_bn_g, h1_bn_b, 64);
    k_apply_h<<<gz64, 256>>>(H, X0, 64);

    // ---- layer 2 via Clenshaw: y_k = x W_k (width 32), then 3 width-32 SpMMs ----
    // y0=SA, y1=SB, y2=SC, y3=H
    k_combine4<8><<<(VN + 15) / 16, 256>>>(X0, h1_w, SA, SB, SC, H);
    // b2 = y2 + 2 L y3        (b2 -> X0)
    k_gather<32, true, false, false><<<gG, 256>>>(2.f, H, SC, 1.f, nullptr, 0.f, X0, 0, nullptr, nullptr, nullptr);
    // b1 = y1 + 2 L b2 - y3   (b1 -> SC, y2 dead)
    k_gather<32, true, true, false><<<gG, 256>>>(2.f, X0, SB, 1.f, H, -1.f, SC, 0, nullptr, nullptr, nullptr);
    // out = relu(y0 + L b1 - b2 + bias + xn), transposed to (B,32,V)
    k_gather<32, true, true, true><<<gG, 256>>>(1.f, SC, SA, 1.f, X0, -1.f, nullptr, 0, h1_b, XN, out);
}

// round 5
// speedup vs baseline: 2.8800x; 1.2384x over previous
#include <cuda_runtime.h>
#include <cuda_fp16.h>

#define VN 100000
#define EN 1600000
#define BATCH 4
#define BN_EPS 1e-5f
#define NB_SCAN 98   // ceil(VN/1024)

// ---------------- static device scratch (no allocations allowed) ----------------
// feature tensors stored fp16, layout (V, C, B): element (v,c,b) at ((v*C+c)*4+b)
__device__ __align__(256) __half g_XN[VN * 32 * BATCH];   // BN'ed input
__device__ __align__(256) __half g_X0[VN * 64 * BATCH];   // hidden input / b2
__device__ __align__(256) __half g_SA[VN * 64 * BATCH];   // x1 / y0
__device__ __align__(256) __half g_SB[VN * 64 * BATCH];   // x2 / y1
__device__ __align__(256) __half g_SC[VN * 64 * BATCH];   // x3 / y2 / b1
__device__ __align__(256) float  g_H [VN * 64 * BATCH];   // layer pre-relu (fp32; low half reused as fp16 y3)
__device__ float g_red[128];
__device__ float g_scale[64];
__device__ float g_shift[64];

// CSR scratch
__device__ __align__(256) int   g_deg[VN];
__device__ __align__(256) int   g_rowptr[VN + 1];
__device__ __align__(256) int   g_cursor[VN];
__device__ __align__(256) int   g_ecol[EN];
__device__ __align__(256) float g_eval[EN];
__device__ int g_bsum[128];
__device__ int g_boff[128];

// ---------------- fp16 pack/unpack helpers (8 values = 2 channels x 4 batch) ----------------
__device__ __forceinline__ void fma8(float* acc, float w, uint4 q) {
    half2* h = (half2*)&q;
#pragma unroll
    for (int t = 0; t < 4; t++) {
        float2 f = __half22float2(h[t]);
        acc[2 * t]     += w * f.x;
        acc[2 * t + 1] += w * f.y;
    }
}
__device__ __forceinline__ void axpy8(float* r, float s, uint4 q) {
    half2* h = (half2*)&q;
#pragma unroll
    for (int t = 0; t < 4; t++) {
        float2 f = __half22float2(h[t]);
        r[2 * t]     += s * f.x;
        r[2 * t + 1] += s * f.y;
    }
}
__device__ __forceinline__ uint4 pack8(const float* r) {
    uint4 q;
    half2* h = (half2*)&q;
#pragma unroll
    for (int t = 0; t < 4; t++) h[t] = __floats2half2_rn(r[2 * t], r[2 * t + 1]);
    return q;
}

// ---------------- CSR build ----------------
__global__ void k_deg_zero() {
    int i = blockIdx.x * 256 + threadIdx.x;
    if (i < VN) g_deg[i] = 0;
    if (i < 128) g_red[i] = 0.f;
}

__global__ void k_hist(const int* __restrict__ rows) {
    int e = blockIdx.x * 256 + threadIdx.x;
    if (e < EN) atomicAdd(&g_deg[rows[e]], 1);
}

__global__ void k_bsum() {
    __shared__ int sh[1024];
    int i = blockIdx.x * 1024 + threadIdx.x;
    sh[threadIdx.x] = (i < VN) ? g_deg[i] : 0;
    __syncthreads();
    for (int off = 512; off > 0; off >>= 1) {
        if (threadIdx.x < off) sh[threadIdx.x] += sh[threadIdx.x + off];
        __syncthreads();
    }
    if (threadIdx.x == 0) g_bsum[blockIdx.x] = sh[0];
}

__global__ void k_bscan() {
    __shared__ int sh[128];
    int t = threadIdx.x;
    int v = (t < NB_SCAN) ? g_bsum[t] : 0;
    sh[t] = v;
    __syncthreads();
    for (int off = 1; off < 128; off <<= 1) {
        int tmp = (t >= off) ? sh[t - off] : 0;
        __syncthreads();
        sh[t] += tmp;
        __syncthreads();
    }
    g_boff[t] = sh[t] - v;
    if (t == 0) g_rowptr[VN] = EN;
}

__global__ void k_scan_final() {
    __shared__ int sh[1024];
    int t = threadIdx.x;
    int i = blockIdx.x * 1024 + t;
    int v = (i < VN) ? g_deg[i] : 0;
    sh[t] = v;
    __syncthreads();
    for (int off = 1; off < 1024; off <<= 1) {
        int tmp = (t >= off) ? sh[t - off] : 0;
        __syncthreads();
        sh[t] += tmp;
        __syncthreads();
    }
    if (i < VN) {
        int excl = g_boff[blockIdx.x] + sh[t] - v;
        g_rowptr[i] = excl;
        g_cursor[i] = excl;
    }
}

__global__ void k_fill(const int* __restrict__ rows, const int* __restrict__ cols,
                       const float* __restrict__ vals) {
    int e = blockIdx.x * 256 + threadIdx.x;
    if (e < EN) {
        int r = rows[e];
        int pos = atomicAdd(&g_cursor[r], 1);
        g_ecol[pos] = cols[e];
        g_eval[pos] = vals[e];
    }
}

// ---------------- BN stats on raw input x, layout (B, C, V) ----------------
__global__ void k_stats_in(const float* __restrict__ x, int C) {
    int c = blockIdx.y;
    float s1 = 0.f, s2 = 0.f;
    for (int v = blockIdx.x * blockDim.x + threadIdx.x; v < VN; v += gridDim.x * blockDim.x) {
#pragma unroll
        for (int b = 0; b < BATCH; b++) {
            float t = x[(b * C + c) * VN + v];
            s1 += t; s2 += t * t;
        }
    }
    __shared__ float sh1[256], sh2[256];
    sh1[threadIdx.x] = s1; sh2[threadIdx.x] = s2;
    __syncthreads();
    for (int off = 128; off > 0; off >>= 1) {
        if (threadIdx.x < off) {
            sh1[threadIdx.x] += sh1[threadIdx.x + off];
            sh2[threadIdx.x] += sh2[threadIdx.x + off];
        }
        __syncthreads();
    }
    if (threadIdx.x == 0) {
        atomicAdd(&g_red[c], sh1[0]);
        atomicAdd(&g_red[64 + c], sh2[0]);
    }
}

// ---------------- BN finalize ----------------
__global__ void k_finalize(const float* __restrict__ gam, const float* __restrict__ bet, int C) {
    int c = threadIdx.x;
    float sc = 0.f, sf = 0.f;
    if (c < C) {
        float n = (float)VN * (float)BATCH;
        float m = g_red[c] / n;
        float var = g_red[64 + c] / n - m * m;
        sc = gam[c] * rsqrtf(var + BN_EPS);
        sf = bet[c] - m * sc;
    }
    __syncthreads();
    if (c < C) { g_scale[c] = sc; g_shift[c] = sf; }
    g_red[c] = 0.f;
}

// ---------------- apply input BN with tiled transpose (B,C,V) fp32 -> (V,32,B) fp16 ----------------
__global__ void k_apply_in(const float* __restrict__ x, uint2* __restrict__ xn) {
    __shared__ uint2 tile[64 * 33];
    int v0 = blockIdx.x * 64;
    for (int i = threadIdx.x; i < 32 * 64; i += 256) {
        int c = i >> 6, vi = i & 63;
        int v = v0 + vi;
        uint2 q = make_uint2(0u, 0u);
        if (v < VN) {
            float sc = g_scale[c], sf = g_shift[c];
            float r0 = sc * x[(0 * 32 + c) * VN + v] + sf;
            float r1 = sc * x[(1 * 32 + c) * VN + v] + sf;
            float r2 = sc * x[(2 * 32 + c) * VN + v] + sf;
            float r3 = sc * x[(3 * 32 + c) * VN + v] + sf;
            half2* h = (half2*)&q;
            h[0] = __floats2half2_rn(r0, r1);
            h[1] = __floats2half2_rn(r2, r3);
        }
        tile[vi * 33 + c] = q;
    }
    __syncthreads();
    for (int i = threadIdx.x; i < 32 * 64; i += 256) {
        int vi = i >> 5, c = i & 31;
        int v = v0 + vi;
        if (v < VN) xn[v * 32 + c] = tile[vi * 33 + c];
    }
}

// ---------------- apply hidden BN + relu: H fp32 (V,64,B) -> X0 fp16 ----------------
__global__ void k_apply_h(const float4* __restrict__ H, uint2* __restrict__ Xo) {
    int g = blockIdx.x * 256 + threadIdx.x;
    if (g >= VN * 64) return;
    int c = g & 63;
    float sc = g_scale[c], sf = g_shift[c];
    float4 h = H[g];
    uint2 q;
    half2* hh = (half2*)&q;
    hh[0] = __floats2half2_rn(sc * fmaxf(h.x, 0.f) + sf, sc * fmaxf(h.y, 0.f) + sf);
    hh[1] = __floats2half2_rn(sc * fmaxf(h.z, 0.f) + sf, sc * fmaxf(h.w, 0.f) + sf);
    Xo[g] = q;
}

// ---------------- gather SpMM, fp16 features, lane = 2 channels x 4 batch (uint4) ------------
// RU4 = uint4 per vertex row (32 for C=64, 16 for C=32); lanes-per-vertex = RU4.
// r = coef * (L-gather of X) + s1*Z1 + s2*Z2.
// FINAL (RU4=16): r += bias + xn, relu, transposed fp32 store to (B,32,V).
template<int RU4, bool HASZ1, bool HASZ2, bool FINAL>
__global__ void __launch_bounds__(256) k_gather(
        float coef, const uint4* __restrict__ X,
        const uint4* __restrict__ Z1, float s1,
        const uint4* __restrict__ Z2, float s2,
        uint4* __restrict__ Y,
        const float* __restrict__ bias, const uint4* __restrict__ xn,
        float* __restrict__ outF) {
    const int VPB = 256 / RU4;
    int vs = threadIdx.x / RU4;
    int j  = threadIdx.x % RU4;
    int v  = blockIdx.x * VPB + vs;

    float r[8] = {0.f, 0.f, 0.f, 0.f, 0.f, 0.f, 0.f, 0.f};
    if (v < VN) {
        int s = g_rowptr[v];
        int e = g_rowptr[v + 1];
        float acc[8] = {0.f, 0.f, 0.f, 0.f, 0.f, 0.f, 0.f, 0.f};
        int i = s;
        for (; i < e && (i & 3); i++) {
            fma8(acc, __ldcs(&g_eval[i]), X[__ldcs(&g_ecol[i]) * RU4 + j]);
        }
        for (; i + 4 <= e; i += 4) {
            int4   cc = __ldcs((const int4*)&g_ecol[i]);
            float4 ww = __ldcs((const float4*)&g_eval[i]);
            uint4 q0 = X[cc.x * RU4 + j];
            uint4 q1 = X[cc.y * RU4 + j];
            uint4 q2 = X[cc.z * RU4 + j];
            uint4 q3 = X[cc.w * RU4 + j];
            fma8(acc, ww.x, q0);
            fma8(acc, ww.y, q1);
            fma8(acc, ww.z, q2);
            fma8(acc, ww.w, q3);
        }
        for (; i < e; i++) {
            fma8(acc, __ldcs(&g_eval[i]), X[__ldcs(&g_ecol[i]) * RU4 + j]);
        }
#pragma unroll
        for (int t = 0; t < 8; t++) r[t] = coef * acc[t];
        if (HASZ1) axpy8(r, s1, __ldcs(&Z1[v * RU4 + j]));
        if (HASZ2) axpy8(r, s2, __ldcs(&Z2[v * RU4 + j]));
        if (!FINAL) {
            __stcs(&Y[v * RU4 + j], pack8(r));
        }
    }

    if (FINAL) {
        // RU4 == 16, VPB == 16. r covers ch {2j, 2j+1} x b{0..3}
        __shared__ float tile[16 * 32 * 4];   // [vs][ch][b], 8KB
        if (v < VN) {
            float xr[8] = {0.f, 0.f, 0.f, 0.f, 0.f, 0.f, 0.f, 0.f};
            axpy8(xr, 1.f, xn[v * 16 + j]);
            float b0 = bias[2 * j], b1 = bias[2 * j + 1];
#pragma unroll
            for (int b = 0; b < 4; b++) {
                r[b]     = fmaxf(r[b]     + b0 + xr[b],     0.f);
                r[4 + b] = fmaxf(r[4 + b] + b1 + xr[4 + b], 0.f);
            }
        } else {
#pragma unroll
            for (int t = 0; t < 8; t++) r[t] = 0.f;
        }
#pragma unroll
        for (int b = 0; b < 4; b++) {
            tile[(vs * 32 + 2 * j) * 4 + b]     = r[b];
            tile[(vs * 32 + 2 * j + 1) * 4 + b] = r[4 + b];
        }
        __syncthreads();
        int vl = threadIdx.x & 15;
        int cw = threadIdx.x >> 4;
        int vv = blockIdx.x * 16 + vl;
        if (vv < VN) {
#pragma unroll
            for (int ci = 0; ci < 2; ci++) {
                int c = cw + ci * 16;
#pragma unroll
                for (int b = 0; b < 4; b++) {
                    outF[(b * 32 + c) * VN + vv] = tile[(vl * 32 + c) * 4 + b];
                }
            }
        }
    }
}

// ---------------- combine: H[v,o,:] = bias[o] + sum_kc w[kc,o]*xk[v,kc,:] (fp16 in, fp32 out) --
// Also accumulates BN stats of relu(out) into g_red.
template<int C, int O, int ITER>
__global__ void __launch_bounds__(256) k_combine(
        const uint4* __restrict__ x0, const uint4* __restrict__ x1,
        const uint4* __restrict__ x2, const uint4* __restrict__ x3,
        const float* __restrict__ w, const float* __restrict__ bias,
        float4* __restrict__ outH) {
    const int KC = 4 * C;
    const int RU = C / 2;           // uint4 per (v,k) row
    const int VPB = 256 / O;
    extern __shared__ char smem[];
    float* sW = (float*)smem;                               // KC*O floats
    uint4* sX = (uint4*)(smem + (size_t)KC * O * sizeof(float));  // VPB*4*RU
    __shared__ float sS1[64], sS2[64];
    const int tid = threadIdx.x;

    if (tid < O) { sS1[tid] = 0.f; sS2[tid] = 0.f; }
    for (int i = tid; i < KC * O; i += 256) sW[i] = w[i];

    const int o = tid % O;
    const int vs = tid / O;
    const float bb = bias[o];
    float ls1 = 0.f, ls2 = 0.f;

    for (int it = 0; it < ITER; it++) {
        const int v0 = (blockIdx.x * ITER + it) * VPB;
        __syncthreads();
        for (int i = tid; i < VPB * 4 * RU; i += 256) {
            int vsl = i / (4 * RU);
            int rem = i - vsl * (4 * RU);
            int k = rem / RU, u = rem - k * RU;
            int v = v0 + vsl;
            const uint4* src = (k == 0) ? x0 : (k == 1) ? x1 : (k == 2) ? x2 : x3;
            sX[i] = (v < VN) ? src[v * RU + u] : make_uint4(0u, 0u, 0u, 0u);
        }
        __syncthreads();

        int v = v0 + vs;
        if (v < VN) {
            float4 acc = make_float4(bb, bb, bb, bb);
            const half2* xh = (const half2*)(sX + vs * 4 * RU);
#pragma unroll 8
            for (int kc = 0; kc < KC; kc++) {
                float wv = sW[kc * O + o];
                float2 a = __half22float2(xh[2 * kc]);
                float2 b = __half22float2(xh[2 * kc + 1]);
                acc.x += wv * a.x; acc.y += wv * a.y;
                acc.z += wv * b.x; acc.w += wv * b.y;
            }
            outH[v * O + o] = acc;
            float a = fmaxf(acc.x, 0.f), b = fmaxf(acc.y, 0.f);
            float d = fmaxf(acc.z, 0.f), f = fmaxf(acc.w, 0.f);
            ls1 += a + b + d + f;
            ls2 += a * a + b * b + d * d + f * f;
        }
    }

    atomicAdd(&sS1[o], ls1);
    atomicAdd(&sS2[o], ls2);
    __syncthreads();
    if (tid < O) {
        atomicAdd(&g_red[tid], sS1[tid]);
        atomicAdd(&g_red[64 + tid], sS2[tid]);
    }
}

// ---------------- combine4 (layer 2): y_k[v,o,:] = sum_c w[k,c,o]*x[v,c,:]  (fp16 in/out) -----
template<int ITER>
__global__ void __launch_bounds__(256) k_combine4(
        const uint4* __restrict__ x, const float* __restrict__ w,
        uint2* __restrict__ y0, uint2* __restrict__ y1,
        uint2* __restrict__ y2, uint2* __restrict__ y3) {
    __shared__ float sW[4 * 64 * 32];   // 32KB
    __shared__ uint4 sX[2 * 32];        // 2 vertices x 32 uint4
    const int tid = threadIdx.x;

    for (int i = tid; i < 4 * 64 * 32; i += 256) sW[i] = w[i];

    const int o2 = tid & 127;
    const int k  = o2 >> 5;
    const int o  = o2 & 31;
    const int vs = tid >> 7;
    uint2* yk = (k == 0) ? y0 : (k == 1) ? y1 : (k == 2) ? y2 : y3;
    const float* wk = sW + k * 64 * 32;

    for (int it = 0; it < ITER; it++) {
        const int v0 = (blockIdx.x * ITER + it) * 2;
        __syncthreads();
        for (int i = tid; i < 2 * 32; i += 256) {
            int vsl = i >> 5, u = i & 31;
            int v = v0 + vsl;
            sX[i] = (v < VN) ? x[v * 32 + u] : make_uint4(0u, 0u, 0u, 0u);
        }
        __syncthreads();

        int v = v0 + vs;
        if (v < VN) {
            float4 acc = make_float4(0.f, 0.f, 0.f, 0.f);
            const half2* xh = (const half2*)(sX + vs * 32);
#pragma unroll 8
            for (int c = 0; c < 64; c++) {
                float wv = wk[c * 32 + o];
                float2 a = __half22float2(xh[2 * c]);
                float2 b = __half22float2(xh[2 * c + 1]);
                acc.x += wv * a.x; acc.y += wv * a.y;
                acc.z += wv * b.x; acc.w += wv * b.y;
            }
            uint2 q;
            half2* h = (half2*)&q;
            h[0] = __floats2half2_rn(acc.x, acc.y);
            h[1] = __floats2half2_rn(acc.z, acc.w);
            yk[v * 32 + o] = q;
        }
    }
}

// ---------------- host orchestration ----------------
extern "C" void kernel_launch(void* const* d_in, const int* in_sizes, int n_in,
                              void* d_out, int out_size) {
    const float* x       = (const float*)d_in[0];
    const int*   ei      = (const int*)  d_in[1];
    const float* vals    = (const float*)d_in[2];
    const float* in_bn_g = (const float*)d_in[3];
    const float* in_bn_b = (const float*)d_in[4];
    const float* in_w    = (const float*)d_in[5];
    const float* in_b    = (const float*)d_in[6];
    const float* h0_bn_g = (const float*)d_in[7];
    const float* h0_bn_b = (const float*)d_in[8];
    const float* h0_w    = (const float*)d_in[9];
    const float* h0_b    = (const float*)d_in[10];
    const float* h1_bn_g = (const float*)d_in[11];
    const float* h1_bn_b = (const float*)d_in[12];
    const float* h1_w    = (const float*)d_in[13];
    const float* h1_b    = (const float*)d_in[14];
    float* out = (float*)d_out;

    const int* rows = ei;
    const int* cols = ei + EN;

    void *pXN, *pX0, *pSA, *pSB, *pSC, *pH;
    cudaGetSymbolAddress(&pXN, g_XN);
    cudaGetSymbolAddress(&pX0, g_X0);
    cudaGetSymbolAddress(&pSA, g_SA);
    cudaGetSymbolAddress(&pSB, g_SB);
    cudaGetSymbolAddress(&pSC, g_SC);
    cudaGetSymbolAddress(&pH,  g_H);
    uint4* XN = (uint4*)pXN;
    uint4* X0 = (uint4*)pX0;
    uint4* SA = (uint4*)pSA;
    uint4* SB = (uint4*)pSB;
    uint4* SC = (uint4*)pSC;
    float4* H  = (float4*)pH;
    uint4* HF16 = (uint4*)pH;   // fp16 alias for layer-2 y3

    cudaFuncSetAttribute(k_combine<32, 64, 4>, cudaFuncAttributeMaxDynamicSharedMemorySize, 36864);
    cudaFuncSetAttribute(k_combine<64, 64, 4>, cudaFuncAttributeMaxDynamicSharedMemorySize, 73728);

    const int gz64 = (VN * 64 + 255) / 256;
    const int gE   = (EN + 255) / 256;
    const int gG32 = (VN + 15) / 16;   // RU4=16 gather grid
    const int gG64 = (VN + 7) / 8;     // RU4=32 gather grid
    const int gCMB = (VN + 15) / 16;   // combine grids (ITER=4 * VPB=4)

    // ---- CSR build ----
    k_deg_zero<<<(VN + 255) / 256, 256>>>();
    k_hist<<<gE, 256>>>(rows);
    k_bsum<<<NB_SCAN, 1024>>>();
    k_bscan<<<1, 128>>>();
    k_scan_final<<<NB_SCAN, 1024>>>();
    k_fill<<<gE, 256>>>(rows, cols, vals);

    // ---- input BN ----
    k_stats_in<<<dim3(64, 32), 256>>>(x, 32);
    k_finalize<<<1, 128>>>(in_bn_g, in_bn_b, 32);
    k_apply_in<<<(VN + 63) / 64, 256>>>(x, (uint2*)pXN);

    // ---- layer 0: C=32 -> O=64 ----
    k_gather<16, false, false, false><<<gG32, 256>>>(1.f, XN, nullptr, 0.f, nullptr, 0.f, SA, nullptr, nullptr, nullptr);
    k_gather<16, true,  false, false><<<gG32, 256>>>(2.f, SA, XN, -1.f, nullptr, 0.f, SB, nullptr, nullptr, nullptr);
    k_gather<16, true,  false, false><<<gG32, 256>>>(2.f, SB, SA, -1.f, nullptr, 0.f, SC, nullptr, nullptr, nullptr);
    k_combine<32, 64, 4><<<gCMB, 256, 36864>>>(XN, SA, SB, SC, in_w, in_b, H);

    // ---- BN + relu on hidden 0 (stats fused into combine) ----
    k_finalize<<<1, 128>>>(h0_bn_g, h0_bn_b, 64);
    k_apply_h<<<gz64, 256>>>(H, (uint2*)pX0);

    // ---- layer 1: C=64 -> O=64, single-pass fp16 gathers ----
    k_gather<32, false, false, false><<<gG64, 256>>>(1.f, X0, nullptr, 0.f, nullptr, 0.f, SA, nullptr, nullptr, nullptr);
    k_gather<32, true,  false, false><<<gG64, 256>>>(2.f, SA, X0, -1.f, nullptr, 0.f, SB, nullptr, nullptr, nullptr);
    k_gather<32, true,  false, false><<<gG64, 256>>>(2.f, SB, SA, -1.f, nullptr, 0.f, SC, nullptr, nullptr, nullptr);
    k_combine<64, 64, 4><<<gCMB, 256, 73728>>>(X0, SA, SB, SC, h0_w, h0_b, H);

    // ---- BN + relu on hidden 1 (stats fused into combine) ----
    k_finalize<<<1, 128>>>(h1_bn_g, h1_bn_b, 64);
    k_apply_h<<<gz64, 256>>>(H, (uint2*)pX0);

    // ---- layer 2 via Clenshaw: y_k = x W_k (width 32), then 3 width-32 SpMMs ----
    // y0=SA, y1=SB, y2=SC, y3=HF16
    k_combine4<8><<<(VN + 15) / 16, 256>>>(X0, h1_w, (uint2*)pSA, (uint2*)pSB, (uint2*)pSC, (uint2*)pH);
    // b2 = y2 + 2 L y3          (-> X0)
    k_gather<16, true, false, false><<<gG32, 256>>>(2.f, HF16, SC, 1.f, nullptr, 0.f, X0, nullptr, nullptr, nullptr);
    // b1 = y1 + 2 L b2 - y3     (-> SC)
    k_gather<16, true, true, false><<<gG32, 256>>>(2.f, X0, SB, 1.f, HF16, -1.f, SC, nullptr, nullptr, nullptr);
    // out = relu(y0 + L b1 - b2 + bias + xn), transposed to (B,32,V) fp32
    k_gather<16, true, true, true><<<gG32, 256>>>(1.f, SC, SA, 1.f, X0, -1.f, nullptr, h1_b, XN, out);
}

// round 6
// speedup vs baseline: 2.9375x; 1.0199x over previous
#include <cuda_runtime.h>
#include <cuda_fp16.h>

#define VN 100000
#define EN 1600000
#define BATCH 4
#define BN_EPS 1e-5f
#define NB_SCAN 98   // ceil(VN/1024)

// ---------------- static device scratch (no allocations allowed) ----------------
// feature tensors stored fp16, layout (V, C, B): element (v,c,b) at ((v*C+c)*4+b)
__device__ __align__(256) __half g_XN[VN * 32 * BATCH];   // BN'ed input
__device__ __align__(256) __half g_X0[VN * 64 * BATCH];   // hidden input / b2
__device__ __align__(256) __half g_SA[VN * 64 * BATCH];   // x1 / y0
__device__ __align__(256) __half g_SB[VN * 64 * BATCH];   // x2 / y1
__device__ __align__(256) __half g_SC[VN * 64 * BATCH];   // x3 / y2 / b1
__device__ __align__(256) float  g_H [VN * 64 * BATCH];   // layer pre-relu (fp32; low half reused as fp16 y3)
__device__ float g_red[128];
__device__ float g_scale[64];
__device__ float g_shift[64];

// CSR scratch
__device__ __align__(256) int   g_deg[VN];
__device__ __align__(256) int   g_rowptr[VN + 1];
__device__ __align__(256) int   g_cursor[VN];
__device__ __align__(256) int   g_ecol[EN];
__device__ __align__(256) float g_eval[EN];
__device__ int g_bsum[128];
__device__ int g_boff[128];

// ---------------- fp16 pack/unpack helpers (8 values = 2 channels x 4 batch) ----------------
__device__ __forceinline__ void fma8(float* acc, float w, uint4 q) {
    half2* h = (half2*)&q;
#pragma unroll
    for (int t = 0; t < 4; t++) {
        float2 f = __half22float2(h[t]);
        acc[2 * t]     += w * f.x;
        acc[2 * t + 1] += w * f.y;
    }
}
__device__ __forceinline__ void axpy8(float* r, float s, uint4 q) {
    half2* h = (half2*)&q;
#pragma unroll
    for (int t = 0; t < 4; t++) {
        float2 f = __half22float2(h[t]);
        r[2 * t]     += s * f.x;
        r[2 * t + 1] += s * f.y;
    }
}
__device__ __forceinline__ uint4 pack8(const float* r) {
    uint4 q;
    half2* h = (half2*)&q;
#pragma unroll
    for (int t = 0; t < 4; t++) h[t] = __floats2half2_rn(r[2 * t], r[2 * t + 1]);
    return q;
}

// ---------------- CSR build ----------------
__global__ void k_deg_zero() {
    int i = blockIdx.x * 256 + threadIdx.x;
    if (i < VN) g_deg[i] = 0;
    if (i < 128) g_red[i] = 0.f;
}

__global__ void k_hist(const int* __restrict__ rows) {
    int e = blockIdx.x * 256 + threadIdx.x;
    if (e < EN) atomicAdd(&g_deg[rows[e]], 1);
}

__global__ void k_bsum() {
    __shared__ int sh[1024];
    int i = blockIdx.x * 1024 + threadIdx.x;
    sh[threadIdx.x] = (i < VN) ? g_deg[i] : 0;
    __syncthreads();
    for (int off = 512; off > 0; off >>= 1) {
        if (threadIdx.x < off) sh[threadIdx.x] += sh[threadIdx.x + off];
        __syncthreads();
    }
    if (threadIdx.x == 0) g_bsum[blockIdx.x] = sh[0];
}

__global__ void k_bscan() {
    __shared__ int sh[128];
    int t = threadIdx.x;
    int v = (t < NB_SCAN) ? g_bsum[t] : 0;
    sh[t] = v;
    __syncthreads();
    for (int off = 1; off < 128; off <<= 1) {
        int tmp = (t >= off) ? sh[t - off] : 0;
        __syncthreads();
        sh[t] += tmp;
        __syncthreads();
    }
    g_boff[t] = sh[t] - v;
    if (t == 0) g_rowptr[VN] = EN;
}

__global__ void k_scan_final() {
    __shared__ int sh[1024];
    int t = threadIdx.x;
    int i = blockIdx.x * 1024 + t;
    int v = (i < VN) ? g_deg[i] : 0;
    sh[t] = v;
    __syncthreads();
    for (int off = 1; off < 1024; off <<= 1) {
        int tmp = (t >= off) ? sh[t - off] : 0;
        __syncthreads();
        sh[t] += tmp;
        __syncthreads();
    }
    if (i < VN) {
        int excl = g_boff[blockIdx.x] + sh[t] - v;
        g_rowptr[i] = excl;
        g_cursor[i] = excl;
    }
}

__global__ void k_fill(const int* __restrict__ rows, const int* __restrict__ cols,
                       const float* __restrict__ vals) {
    int e = blockIdx.x * 256 + threadIdx.x;
    if (e < EN) {
        int r = rows[e];
        int pos = atomicAdd(&g_cursor[r], 1);
        g_ecol[pos] = cols[e];
        g_eval[pos] = vals[e];
    }
}

// ---------------- BN stats on raw input x, layout (B, C, V) ----------------
__global__ void k_stats_in(const float* __restrict__ x, int C) {
    int c = blockIdx.y;
    float s1 = 0.f, s2 = 0.f;
    for (int v = blockIdx.x * blockDim.x + threadIdx.x; v < VN; v += gridDim.x * blockDim.x) {
#pragma unroll
        for (int b = 0; b < BATCH; b++) {
            float t = x[(b * C + c) * VN + v];
            s1 += t; s2 += t * t;
        }
    }
    __shared__ float sh1[256], sh2[256];
    sh1[threadIdx.x] = s1; sh2[threadIdx.x] = s2;
    __syncthreads();
    for (int off = 128; off > 0; off >>= 1) {
        if (threadIdx.x < off) {
            sh1[threadIdx.x] += sh1[threadIdx.x + off];
            sh2[threadIdx.x] += sh2[threadIdx.x + off];
        }
        __syncthreads();
    }
    if (threadIdx.x == 0) {
        atomicAdd(&g_red[c], sh1[0]);
        atomicAdd(&g_red[64 + c], sh2[0]);
    }
}

// ---------------- BN finalize ----------------
__global__ void k_finalize(const float* __restrict__ gam, const float* __restrict__ bet, int C) {
    int c = threadIdx.x;
    float sc = 0.f, sf = 0.f;
    if (c < C) {
        float n = (float)VN * (float)BATCH;
        float m = g_red[c] / n;
        float var = g_red[64 + c] / n - m * m;
        sc = gam[c] * rsqrtf(var + BN_EPS);
        sf = bet[c] - m * sc;
    }
    __syncthreads();
    if (c < C) { g_scale[c] = sc; g_shift[c] = sf; }
    g_red[c] = 0.f;
}

// ---------------- apply input BN with tiled transpose (B,C,V) fp32 -> (V,32,B) fp16 ----------------
__global__ void k_apply_in(const float* __restrict__ x, uint2* __restrict__ xn) {
    __shared__ uint2 tile[64 * 33];
    int v0 = blockIdx.x * 64;
    for (int i = threadIdx.x; i < 32 * 64; i += 256) {
        int c = i >> 6, vi = i & 63;
        int v = v0 + vi;
        uint2 q = make_uint2(0u, 0u);
        if (v < VN) {
            float sc = g_scale[c], sf = g_shift[c];
            float r0 = sc * x[(0 * 32 + c) * VN + v] + sf;
            float r1 = sc * x[(1 * 32 + c) * VN + v] + sf;
            float r2 = sc * x[(2 * 32 + c) * VN + v] + sf;
            float r3 = sc * x[(3 * 32 + c) * VN + v] + sf;
            half2* h = (half2*)&q;
            h[0] = __floats2half2_rn(r0, r1);
            h[1] = __floats2half2_rn(r2, r3);
        }
        tile[vi * 33 + c] = q;
    }
    __syncthreads();
    for (int i = threadIdx.x; i < 32 * 64; i += 256) {
        int vi = i >> 5, c = i & 31;
        int v = v0 + vi;
        if (v < VN) xn[v * 32 + c] = tile[vi * 33 + c];
    }
}

// ---------------- apply hidden BN + relu: H fp32 (V,64,B) -> X0 fp16 ----------------
__global__ void k_apply_h(const float4* __restrict__ H, uint2* __restrict__ Xo) {
    int g = blockIdx.x * 256 + threadIdx.x;
    if (g >= VN * 64) return;
    int c = g & 63;
    float sc = g_scale[c], sf = g_shift[c];
    float4 h = H[g];
    uint2 q;
    half2* hh = (half2*)&q;
    hh[0] = __floats2half2_rn(sc * fmaxf(h.x, 0.f) + sf, sc * fmaxf(h.y, 0.f) + sf);
    hh[1] = __floats2half2_rn(sc * fmaxf(h.z, 0.f) + sf, sc * fmaxf(h.w, 0.f) + sf);
    Xo[g] = q;
}

// ---------------- gather SpMM, fp16 features, deep-MLP edge loop ----------------
// RU4 = uint4 per vertex row (32 for C=64, 16 for C=32); lanes-per-vertex = RU4.
// r = coef * (L-gather of X) + s1*Z1 + s2*Z2.
// FINAL (RU4=16): r += bias + xn, relu, transposed fp32 store to (B,32,V).
template<int RU4, bool HASZ1, bool HASZ2, bool FINAL>
__global__ void __launch_bounds__(256) k_gather(
        float coef, const uint4* __restrict__ X,
        const uint4* __restrict__ Z1, float s1,
        const uint4* __restrict__ Z2, float s2,
        uint4* __restrict__ Y,
        const float* __restrict__ bias, const uint4* __restrict__ xn,
        float* __restrict__ outF) {
    const int VPB = 256 / RU4;
    int vs = threadIdx.x / RU4;
    int j  = threadIdx.x % RU4;
    int v  = blockIdx.x * VPB + vs;

    float r[8] = {0.f, 0.f, 0.f, 0.f, 0.f, 0.f, 0.f, 0.f};
    if (v < VN) {
        int s = g_rowptr[v];
        int e = g_rowptr[v + 1];
        float acc[8] = {0.f, 0.f, 0.f, 0.f, 0.f, 0.f, 0.f, 0.f};
        int i = s;
        // peel to 16B-aligned edge index
        for (; i < e && (i & 3); i++) {
            fma8(acc, __ldcs(&g_eval[i]), X[__ldcs(&g_ecol[i]) * RU4 + j]);
        }
        // 8-edge unroll: 8 independent LDG.128 in flight before any consumption
        for (; i + 8 <= e; i += 8) {
            int4   ca = __ldcs((const int4*)&g_ecol[i]);
            int4   cb = __ldcs((const int4*)&g_ecol[i + 4]);
            float4 wa = __ldcs((const float4*)&g_eval[i]);
            float4 wb = __ldcs((const float4*)&g_eval[i + 4]);
            uint4 q0 = X[ca.x * RU4 + j];
            uint4 q1 = X[ca.y * RU4 + j];
            uint4 q2 = X[ca.z * RU4 + j];
            uint4 q3 = X[ca.w * RU4 + j];
            uint4 q4 = X[cb.x * RU4 + j];
            uint4 q5 = X[cb.y * RU4 + j];
            uint4 q6 = X[cb.z * RU4 + j];
            uint4 q7 = X[cb.w * RU4 + j];
            fma8(acc, wa.x, q0);
            fma8(acc, wa.y, q1);
            fma8(acc, wa.z, q2);
            fma8(acc, wa.w, q3);
            fma8(acc, wb.x, q4);
            fma8(acc, wb.y, q5);
            fma8(acc, wb.z, q6);
            fma8(acc, wb.w, q7);
        }
        for (; i + 4 <= e; i += 4) {
            int4   cc = __ldcs((const int4*)&g_ecol[i]);
            float4 ww = __ldcs((const float4*)&g_eval[i]);
            uint4 q0 = X[cc.x * RU4 + j];
            uint4 q1 = X[cc.y * RU4 + j];
            uint4 q2 = X[cc.z * RU4 + j];
            uint4 q3 = X[cc.w * RU4 + j];
            fma8(acc, ww.x, q0);
            fma8(acc, ww.y, q1);
            fma8(acc, ww.z, q2);
            fma8(acc, ww.w, q3);
        }
        for (; i < e; i++) {
            fma8(acc, __ldcs(&g_eval[i]), X[__ldcs(&g_ecol[i]) * RU4 + j]);
        }
#pragma unroll
        for (int t = 0; t < 8; t++) r[t] = coef * acc[t];
        if (HASZ1) axpy8(r, s1, __ldcs(&Z1[v * RU4 + j]));
        if (HASZ2) axpy8(r, s2, __ldcs(&Z2[v * RU4 + j]));
        if (!FINAL) {
            __stcs(&Y[v * RU4 + j], pack8(r));
        }
    }

    if (FINAL) {
        // RU4 == 16, VPB == 16. r covers ch {2j, 2j+1} x b{0..3}
        __shared__ float tile[16 * 32 * 4];   // [vs][ch][b], 8KB
        if (v < VN) {
            float xr[8] = {0.f, 0.f, 0.f, 0.f, 0.f, 0.f, 0.f, 0.f};
            axpy8(xr, 1.f, xn[v * 16 + j]);
            float b0 = bias[2 * j], b1 = bias[2 * j + 1];
#pragma unroll
            for (int b = 0; b < 4; b++) {
                r[b]     = fmaxf(r[b]     + b0 + xr[b],     0.f);
                r[4 + b] = fmaxf(r[4 + b] + b1 + xr[4 + b], 0.f);
            }
        } else {
#pragma unroll
            for (int t = 0; t < 8; t++) r[t] = 0.f;
        }
#pragma unroll
        for (int b = 0; b < 4; b++) {
            tile[(vs * 32 + 2 * j) * 4 + b]     = r[b];
            tile[(vs * 32 + 2 * j + 1) * 4 + b] = r[4 + b];
        }
        __syncthreads();
        int vl = threadIdx.x & 15;
        int cw = threadIdx.x >> 4;
        int vv = blockIdx.x * 16 + vl;
        if (vv < VN) {
#pragma unroll
            for (int ci = 0; ci < 2; ci++) {
                int c = cw + ci * 16;
#pragma unroll
                for (int b = 0; b < 4; b++) {
                    outF[(b * 32 + c) * VN + vv] = tile[(vl * 32 + c) * 4 + b];
                }
            }
        }
    }
}

// ---------------- combine: H[v,o,:] = bias[o] + sum_kc w[kc,o]*xk[v,kc,:] (fp16 in, fp32 out) --
// Also accumulates BN stats of relu(out) into g_red.
template<int C, int O, int ITER>
__global__ void __launch_bounds__(256) k_combine(
        const uint4* __restrict__ x0, const uint4* __restrict__ x1,
        const uint4* __restrict__ x2, const uint4* __restrict__ x3,
        const float* __restrict__ w, const float* __restrict__ bias,
        float4* __restrict__ outH) {
    const int KC = 4 * C;
    const int RU = C / 2;           // uint4 per (v,k) row
    const int VPB = 256 / O;
    extern __shared__ char smem[];
    float* sW = (float*)smem;                               // KC*O floats
    uint4* sX = (uint4*)(smem + (size_t)KC * O * sizeof(float));  // VPB*4*RU
    __shared__ float sS1[64], sS2[64];
    const int tid = threadIdx.x;

    if (tid < O) { sS1[tid] = 0.f; sS2[tid] = 0.f; }
    for (int i = tid; i < KC * O; i += 256) sW[i] = w[i];

    const int o = tid % O;
    const int vs = tid / O;
    const float bb = bias[o];
    float ls1 = 0.f, ls2 = 0.f;

    for (int it = 0; it < ITER; it++) {
        const int v0 = (blockIdx.x * ITER + it) * VPB;
        __syncthreads();
        for (int i = tid; i < VPB * 4 * RU; i += 256) {
            int vsl = i / (4 * RU);
            int rem = i - vsl * (4 * RU);
            int k = rem / RU, u = rem - k * RU;
            int v = v0 + vsl;
            const uint4* src = (k == 0) ? x0 : (k == 1) ? x1 : (k == 2) ? x2 : x3;
            sX[i] = (v < VN) ? src[v * RU + u] : make_uint4(0u, 0u, 0u, 0u);
        }
        __syncthreads();

        int v = v0 + vs;
        if (v < VN) {
            float4 acc = make_float4(bb, bb, bb, bb);
            const half2* xh = (const half2*)(sX + vs * 4 * RU);
#pragma unroll 8
            for (int kc = 0; kc < KC; kc++) {
                float wv = sW[kc * O + o];
                float2 a = __half22float2(xh[2 * kc]);
                float2 b = __half22float2(xh[2 * kc + 1]);
                acc.x += wv * a.x; acc.y += wv * a.y;
                acc.z += wv * b.x; acc.w += wv * b.y;
            }
            outH[v * O + o] = acc;
            float a = fmaxf(acc.x, 0.f), b = fmaxf(acc.y, 0.f);
            float d = fmaxf(acc.z, 0.f), f = fmaxf(acc.w, 0.f);
            ls1 += a + b + d + f;
            ls2 += a * a + b * b + d * d + f * f;
        }
    }

    atomicAdd(&sS1[o], ls1);
    atomicAdd(&sS2[o], ls2);
    __syncthreads();
    if (tid < O) {
        atomicAdd(&g_red[tid], sS1[tid]);
        atomicAdd(&g_red[64 + tid], sS2[tid]);
    }
}

// ---------------- combine4 (layer 2): y_k[v,o,:] = sum_c w[k,c,o]*x[v,c,:]  (fp16 in/out) -----
template<int ITER>
__global__ void __launch_bounds__(256) k_combine4(
        const uint4* __restrict__ x, const float* __restrict__ w,
        uint2* __restrict__ y0, uint2* __restrict__ y1,
        uint2* __restrict__ y2, uint2* __restrict__ y3) {
    __shared__ float sW[4 * 64 * 32];   // 32KB
    __shared__ uint4 sX[2 * 32];        // 2 vertices x 32 uint4
    const int tid = threadIdx.x;

    for (int i = tid; i < 4 * 64 * 32; i += 256) sW[i] = w[i];

    const int o2 = tid & 127;
    const int k  = o2 >> 5;
    const int o  = o2 & 31;
    const int vs = tid >> 7;
    uint2* yk = (k == 0) ? y0 : (k == 1) ? y1 : (k == 2) ? y2 : y3;
    const float* wk = sW + k * 64 * 32;

    for (int it = 0; it < ITER; it++) {
        const int v0 = (blockIdx.x * ITER + it) * 2;
        __syncthreads();
        for (int i = tid; i < 2 * 32; i += 256) {
            int vsl = i >> 5, u = i & 31;
            int v = v0 + vsl;
            sX[i] = (v < VN) ? x[v * 32 + u] : make_uint4(0u, 0u, 0u, 0u);
        }
        __syncthreads();

        int v = v0 + vs;
        if (v < VN) {
            float4 acc = make_float4(0.f, 0.f, 0.f, 0.f);
            const half2* xh = (const half2*)(sX + vs * 32);
#pragma unroll 8
            for (int c = 0; c < 64; c++) {
                float wv = wk[c * 32 + o];
                float2 a = __half22float2(xh[2 * c]);
                float2 b = __half22float2(xh[2 * c + 1]);
                acc.x += wv * a.x; acc.y += wv * a.y;
                acc.z += wv * b.x; acc.w += wv * b.y;
            }
            uint2 q;
            half2* h = (half2*)&q;
            h[0] = __floats2half2_rn(acc.x, acc.y);
            h[1] = __floats2half2_rn(acc.z, acc.w);
            yk[v * 32 + o] = q;
        }
    }
}

// ---------------- host orchestration ----------------
extern "C" void kernel_launch(void* const* d_in, const int* in_sizes, int n_in,
                              void* d_out, int out_size) {
    const float* x       = (const float*)d_in[0];
    const int*   ei      = (const int*)  d_in[1];
    const float* vals    = (const float*)d_in[2];
    const float* in_bn_g = (const float*)d_in[3];
    const float* in_bn_b = (const float*)d_in[4];
    const float* in_w    = (const float*)d_in[5];
    const float* in_b    = (const float*)d_in[6];
    const float* h0_bn_g = (const float*)d_in[7];
    const float* h0_bn_b = (const float*)d_in[8];
    const float* h0_w    = (const float*)d_in[9];
    const float* h0_b    = (const float*)d_in[10];
    const float* h1_bn_g = (const float*)d_in[11];
    const float* h1_bn_b = (const float*)d_in[12];
    const float* h1_w    = (const float*)d_in[13];
    const float* h1_b    = (const float*)d_in[14];
    float* out = (float*)d_out;

    const int* rows = ei;
    const int* cols = ei + EN;

    void *pXN, *pX0, *pSA, *pSB, *pSC, *pH;
    cudaGetSymbolAddress(&pXN, g_XN);
    cudaGetSymbolAddress(&pX0, g_X0);
    cudaGetSymbolAddress(&pSA, g_SA);
    cudaGetSymbolAddress(&pSB, g_SB);
    cudaGetSymbolAddress(&pSC, g_SC);
    cudaGetSymbolAddress(&pH,  g_H);
    uint4* XN = (uint4*)pXN;
    uint4* X0 = (uint4*)pX0;
    uint4* SA = (uint4*)pSA;
    uint4* SB = (uint4*)pSB;
    uint4* SC = (uint4*)pSC;
    float4* H  = (float4*)pH;
    uint4* HF16 = (uint4*)pH;   // fp16 alias for layer-2 y3

    cudaFuncSetAttribute(k_combine<32, 64, 4>, cudaFuncAttributeMaxDynamicSharedMemorySize, 36864);
    cudaFuncSetAttribute(k_combine<64, 64, 4>, cudaFuncAttributeMaxDynamicSharedMemorySize, 73728);

    const int gz64 = (VN * 64 + 255) / 256;
    const int gE   = (EN + 255) / 256;
    const int gG32 = (VN + 15) / 16;   // RU4=16 gather grid
    const int gG64 = (VN + 7) / 8;     // RU4=32 gather grid
    const int gCMB = (VN + 15) / 16;   // combine grids (ITER=4 * VPB=4)

    // ---- CSR build ----
    k_deg_zero<<<(VN + 255) / 256, 256>>>();
    k_hist<<<gE, 256>>>(rows);
    k_bsum<<<NB_SCAN, 1024>>>();
    k_bscan<<<1, 128>>>();
    k_scan_final<<<NB_SCAN, 1024>>>();
    k_fill<<<gE, 256>>>(rows, cols, vals);

    // ---- input BN ----
    k_stats_in<<<dim3(64, 32), 256>>>(x, 32);
    k_finalize<<<1, 128>>>(in_bn_g, in_bn_b, 32);
    k_apply_in<<<(VN + 63) / 64, 256>>>(x, (uint2*)pXN);

    // ---- layer 0: C=32 -> O=64 ----
    k_gather<16, false, false, false><<<gG32, 256>>>(1.f, XN, nullptr, 0.f, nullptr, 0.f, SA, nullptr, nullptr, nullptr);
    k_gather<16, true,  false, false><<<gG32, 256>>>(2.f, SA, XN, -1.f, nullptr, 0.f, SB, nullptr, nullptr, nullptr);
    k_gather<16, true,  false, false><<<gG32, 256>>>(2.f, SB, SA, -1.f, nullptr, 0.f, SC, nullptr, nullptr, nullptr);
    k_combine<32, 64, 4><<<gCMB, 256, 36864>>>(XN, SA, SB, SC, in_w, in_b, H);

    // ---- BN + relu on hidden 0 (stats fused into combine) ----
    k_finalize<<<1, 128>>>(h0_bn_g, h0_bn_b, 64);
    k_apply_h<<<gz64, 256>>>(H, (uint2*)pX0);

    // ---- layer 1: C=64 -> O=64, single-pass fp16 gathers ----
    k_gather<32, false, false, false><<<gG64, 256>>>(1.f, X0, nullptr, 0.f, nullptr, 0.f, SA, nullptr, nullptr, nullptr);
    k_gather<32, true,  false, false><<<gG64, 256>>>(2.f, SA, X0, -1.f, nullptr, 0.f, SB, nullptr, nullptr, nullptr);
    k_gather<32, true,  false, false><<<gG64, 256>>>(2.f, SB, SA, -1.f, nullptr, 0.f, SC, nullptr, nullptr, nullptr);
    k_combine<64, 64, 4><<<gCMB, 256, 73728>>>(X0, SA, SB, SC, h0_w, h0_b, H);

    // ---- BN + relu on hidden 1 (stats fused into combine) ----
    k_finalize<<<1, 128>>>(h1_bn_g, h1_bn_b, 64);
    k_apply_h<<<gz64, 256>>>(H, (uint2*)pX0);

    // ---- layer 2 via Clenshaw: y_k = x W_k (width 32), then 3 width-32 SpMMs ----
    // y0=SA, y1=SB, y2=SC, y3=HF16
    k_combine4<8><<<(VN + 15) / 16, 256>>>(X0, h1_w, (uint2*)pSA, (uint2*)pSB, (uint2*)pSC, (uint2*)pH);
    // b2 = y2 + 2 L y3          (-> X0)
    k_gather<16, true, false, false><<<gG32, 256>>>(2.f, HF16, SC, 1.f, nullptr, 0.f, X0, nullptr, nullptr, nullptr);
    // b1 = y1 + 2 L b2 - y3     (-> SC)
    k_gather<16, true, true, false><<<gG32, 256>>>(2.f, X0, SB, 1.f, HF16, -1.f, SC, nullptr, nullptr, nullptr);
    // out = relu(y0 + L b1 - b2 + bias + xn), transposed to (B,32,V) fp32
    k_gather<16, true, true, true><<<gG32, 256>>>(1.f, SC, SA, 1.f, X0, -1.f, nullptr, h1_b, XN, out);
}

// round 7
// speedup vs baseline: 3.0110x; 1.0250x over previous
#include <cuda_runtime.h>
#include <cuda_fp16.h>

#define VN 100000
#define EN 1600000
#define BATCH 4
#define BN_EPS 1e-5f
#define NB_SCAN 98   // ceil(VN/1024)

// ---------------- static device scratch (no allocations allowed) ----------------
// feature tensors fp16, layout (V, C, B): element (v,c,b) at ((v*C+c)*4+b)
__device__ __align__(256) __half g_XN[VN * 32 * BATCH];   // BN'ed input (true x0 of layer 0)
__device__ __align__(256) __half g_R1[VN * 64 * BATCH];   // relu(H1) / b2
__device__ __align__(256) __half g_SA[VN * 64 * BATCH];   // x1 / y0^
__device__ __align__(256) __half g_SB[VN * 64 * BATCH];   // x2 / y1^
__device__ __align__(256) __half g_SC[VN * 64 * BATCH];   // x3 / y2^ / b1
__device__ __align__(256) __half g_R0[VN * 64 * BATCH];   // relu(H0) / y3^
__device__ float g_red[128];
__device__ float g_scale[64];
__device__ float g_shift[64];

// folded weights / constant vectors
__device__ float g_wf[4 * 64 * 64];   // layer-1 weights, k=0 slice scaled
__device__ float g_bf[64];            // layer-1 folded bias
__device__ float g_wf2[4 * 64 * 32];  // layer-2 weights, all k scaled
__device__ float g_qb2[32], g_pb2[32], g_qb1[32], g_qout[32];

// CSR scratch
__device__ __align__(256) int   g_deg[VN];
__device__ __align__(256) int   g_rowptr[VN + 1];
__device__ __align__(256) int   g_cursor[VN];
__device__ __align__(256) float g_rowsum[VN];
__device__ __align__(256) int   g_ecol[EN];
__device__ __align__(256) float g_eval[EN];
__device__ int g_bsum[128];
__device__ int g_boff[128];

// ---------------- fp16 helpers (8 values = 2 channels x 4 batch) ----------------
__device__ __forceinline__ void fma8(float* acc, float w, uint4 q) {
    half2* h = (half2*)&q;
#pragma unroll
    for (int t = 0; t < 4; t++) {
        float2 f = __half22float2(h[t]);
        acc[2 * t]     += w * f.x;
        acc[2 * t + 1] += w * f.y;
    }
}
__device__ __forceinline__ void unpack8(float* z, uint4 q) {
    half2* h = (half2*)&q;
#pragma unroll
    for (int t = 0; t < 4; t++) {
        float2 f = __half22float2(h[t]);
        z[2 * t] = f.x; z[2 * t + 1] = f.y;
    }
}
__device__ __forceinline__ uint4 pack8(const float* r) {
    uint4 q;
    half2* h = (half2*)&q;
#pragma unroll
    for (int t = 0; t < 4; t++) h[t] = __floats2half2_rn(r[2 * t], r[2 * t + 1]);
    return q;
}

// ---------------- CSR build ----------------
__global__ void k_deg_zero() {
    int i = blockIdx.x * 256 + threadIdx.x;
    if (i < VN) { g_deg[i] = 0; g_rowsum[i] = 0.f; }
    if (i < 128) g_red[i] = 0.f;
}

__global__ void k_hist(const int* __restrict__ rows) {
    int e = blockIdx.x * 256 + threadIdx.x;
    if (e < EN) atomicAdd(&g_deg[rows[e]], 1);
}

__global__ void k_bsum() {
    __shared__ int sh[1024];
    int i = blockIdx.x * 1024 + threadIdx.x;
    sh[threadIdx.x] = (i < VN) ? g_deg[i] : 0;
    __syncthreads();
    for (int off = 512; off > 0; off >>= 1) {
        if (threadIdx.x < off) sh[threadIdx.x] += sh[threadIdx.x + off];
        __syncthreads();
    }
    if (threadIdx.x == 0) g_bsum[blockIdx.x] = sh[0];
}

__global__ void k_bscan() {
    __shared__ int sh[128];
    int t = threadIdx.x;
    int v = (t < NB_SCAN) ? g_bsum[t] : 0;
    sh[t] = v;
    __syncthreads();
    for (int off = 1; off < 128; off <<= 1) {
        int tmp = (t >= off) ? sh[t - off] : 0;
        __syncthreads();
        sh[t] += tmp;
        __syncthreads();
    }
    g_boff[t] = sh[t] - v;
    if (t == 0) g_rowptr[VN] = EN;
}

__global__ void k_scan_final() {
    __shared__ int sh[1024];
    int t = threadIdx.x;
    int i = blockIdx.x * 1024 + t;
    int v = (i < VN) ? g_deg[i] : 0;
    sh[t] = v;
    __syncthreads();
    for (int off = 1; off < 1024; off <<= 1) {
        int tmp = (t >= off) ? sh[t - off] : 0;
        __syncthreads();
        sh[t] += tmp;
        __syncthreads();
    }
    if (i < VN) {
        int excl = g_boff[blockIdx.x] + sh[t] - v;
        g_rowptr[i] = excl;
        g_cursor[i] = excl;
    }
}

__global__ void k_fill(const int* __restrict__ rows, const int* __restrict__ cols,
                       const float* __restrict__ vals) {
    int e = blockIdx.x * 256 + threadIdx.x;
    if (e < EN) {
        int r = rows[e];
        float w = vals[e];
        int pos = atomicAdd(&g_cursor[r], 1);
        g_ecol[pos] = cols[e];
        g_eval[pos] = w;
        atomicAdd(&g_rowsum[r], w);
    }
}

// ---------------- BN stats on raw input x, layout (B, C, V) ----------------
__global__ void k_stats_in(const float* __restrict__ x, int C) {
    int c = blockIdx.y;
    float s1 = 0.f, s2 = 0.f;
    for (int v = blockIdx.x * blockDim.x + threadIdx.x; v < VN; v += gridDim.x * blockDim.x) {
#pragma unroll
        for (int b = 0; b < BATCH; b++) {
            float t = x[(b * C + c) * VN + v];
            s1 += t; s2 += t * t;
        }
    }
    __shared__ float sh1[256], sh2[256];
    sh1[threadIdx.x] = s1; sh2[threadIdx.x] = s2;
    __syncthreads();
    for (int off = 128; off > 0; off >>= 1) {
        if (threadIdx.x < off) {
            sh1[threadIdx.x] += sh1[threadIdx.x + off];
            sh2[threadIdx.x] += sh2[threadIdx.x + off];
        }
        __syncthreads();
    }
    if (threadIdx.x == 0) {
        atomicAdd(&g_red[c], sh1[0]);
        atomicAdd(&g_red[64 + c], sh2[0]);
    }
}

// ---------------- BN finalize ----------------
__global__ void k_finalize(const float* __restrict__ gam, const float* __restrict__ bet, int C) {
    int c = threadIdx.x;
    float sc = 0.f, sf = 0.f;
    if (c < C) {
        float n = (float)VN * (float)BATCH;
        float m = g_red[c] / n;
        float var = g_red[64 + c] / n - m * m;
        sc = gam[c] * rsqrtf(var + BN_EPS);
        sf = bet[c] - m * sc;
    }
    __syncthreads();
    if (c < C) { g_scale[c] = sc; g_shift[c] = sf; }
    g_red[c] = 0.f;
}

// ---------------- fold layer-1 weights: k=0 slice scaled, folded bias ----------------
__global__ void k_fold1(const float* __restrict__ w, const float* __restrict__ bias) {
    int t = blockIdx.x * 256 + threadIdx.x;   // 4*64*64 = 16384
    if (t < 16384) {
        int k = t >> 12;
        int c = (t >> 6) & 63;
        float wv = w[t];
        g_wf[t] = (k == 0) ? wv * g_scale[c] : wv;
    }
    if (blockIdx.x == 0 && threadIdx.x < 64) {
        int o = threadIdx.x;
        float s = bias[o];
        for (int c = 0; c < 64; c++) s += w[c * 64 + o] * g_shift[c];
        g_bf[o] = s;
    }
}

// ---------------- fold layer-2 weights: all k scaled; build Clenshaw const vectors ----------
__global__ void k_fold2(const float* __restrict__ w) {
    int t = blockIdx.x * 256 + threadIdx.x;   // 4*64*32 = 8192
    if (t < 8192) {
        int c = (t >> 5) & 63;
        g_wf2[t] = w[t] * g_scale[c];
    }
    if (blockIdx.x == 0) {
        __shared__ float su[4 * 32];
        if (threadIdx.x < 128) {
            int k = threadIdx.x >> 5, o = threadIdx.x & 31;
            float u = 0.f;
            for (int c = 0; c < 64; c++) u += w[k * 2048 + c * 32 + o] * g_shift[c];
            su[threadIdx.x] = u;
        }
        __syncthreads();
        if (threadIdx.x < 32) {
            int o = threadIdx.x;
            g_qb2[o]  = su[2 * 32 + o];
            g_pb2[o]  = 2.f * su[3 * 32 + o];
            g_qb1[o]  = su[1 * 32 + o] - su[3 * 32 + o];
            g_qout[o] = su[0 * 32 + o];
        }
    }
}

// ---------------- apply input BN with tiled transpose (B,C,V) fp32 -> (V,32,B) fp16 ----------------
__global__ void k_apply_in(const float* __restrict__ x, uint2* __restrict__ xn) {
    __shared__ uint2 tile[64 * 33];
    int v0 = blockIdx.x * 64;
    for (int i = threadIdx.x; i < 32 * 64; i += 256) {
        int c = i >> 6, vi = i & 63;
        int v = v0 + vi;
        uint2 q = make_uint2(0u, 0u);
        if (v < VN) {
            float sc = g_scale[c], sf = g_shift[c];
            float r0 = sc * x[(0 * 32 + c) * VN + v] + sf;
            float r1 = sc * x[(1 * 32 + c) * VN + v] + sf;
            float r2 = sc * x[(2 * 32 + c) * VN + v] + sf;
            float r3 = sc * x[(3 * 32 + c) * VN + v] + sf;
            half2* h = (half2*)&q;
            h[0] = __floats2half2_rn(r0, r1);
            h[1] = __floats2half2_rn(r2, r3);
        }
        tile[vi * 33 + c] = q;
    }
    __syncthreads();
    for (int i = threadIdx.x; i < 32 * 64; i += 256) {
        int vi = i >> 5, c = i & 31;
        int v = v0 + vi;
        if (v < VN) xn[v * 32 + c] = tile[vi * 33 + c];
    }
}

// ---------------- gather SpMM, fp16 features ----------------
// r = coef*(gather of X [optionally affine: sc*acc + sf*rowsum]) + s1*Z1[opt affine] + s2*Z2
//     [+ q_ch] [+ rowsum*p_ch]
// FINAL (RU4=16): r += bias + xn, relu, transposed fp32 store to (B,32,V).
template<int RU4, bool AFFX, bool HASZ1, bool AFFZ1, bool HASZ2, bool HASP, bool HASQ, bool FINAL>
__global__ void __launch_bounds__(256) k_gather(
        float coef, const uint4* __restrict__ X,
        const uint4* __restrict__ Z1, float s1,
        const uint4* __restrict__ Z2, float s2,
        uint4* __restrict__ Y,
        const float* __restrict__ qv, const float* __restrict__ pv,
        const float* __restrict__ bias, const uint4* __restrict__ xn,
        float* __restrict__ outF) {
    const int VPB = 256 / RU4;
    int vs = threadIdx.x / RU4;
    int j  = threadIdx.x % RU4;
    int v  = blockIdx.x * VPB + vs;

    float r[8] = {0.f, 0.f, 0.f, 0.f, 0.f, 0.f, 0.f, 0.f};
    if (v < VN) {
        int s = g_rowptr[v];
        int e = g_rowptr[v + 1];
        float acc[8] = {0.f, 0.f, 0.f, 0.f, 0.f, 0.f, 0.f, 0.f};
        int i = s;
        for (; i < e && (i & 3); i++) {
            fma8(acc, __ldcs(&g_eval[i]), X[__ldcs(&g_ecol[i]) * RU4 + j]);
        }
        for (; i + 8 <= e; i += 8) {
            int4   ca = __ldcs((const int4*)&g_ecol[i]);
            int4   cb = __ldcs((const int4*)&g_ecol[i + 4]);
            float4 wa = __ldcs((const float4*)&g_eval[i]);
            float4 wb = __ldcs((const float4*)&g_eval[i + 4]);
            uint4 q0 = X[ca.x * RU4 + j];
            uint4 q1 = X[ca.y * RU4 + j];
            uint4 q2 = X[ca.z * RU4 + j];
            uint4 q3 = X[ca.w * RU4 + j];
            uint4 q4 = X[cb.x * RU4 + j];
            uint4 q5 = X[cb.y * RU4 + j];
            uint4 q6 = X[cb.z * RU4 + j];
            uint4 q7 = X[cb.w * RU4 + j];
            fma8(acc, wa.x, q0);
            fma8(acc, wa.y, q1);
            fma8(acc, wa.z, q2);
            fma8(acc, wa.w, q3);
            fma8(acc, wb.x, q4);
            fma8(acc, wb.y, q5);
            fma8(acc, wb.z, q6);
            fma8(acc, wb.w, q7);
        }
        for (; i + 4 <= e; i += 4) {
            int4   cc = __ldcs((const int4*)&g_ecol[i]);
            float4 ww = __ldcs((const float4*)&g_eval[i]);
            uint4 q0 = X[cc.x * RU4 + j];
            uint4 q1 = X[cc.y * RU4 + j];
            uint4 q2 = X[cc.z * RU4 + j];
            uint4 q3 = X[cc.w * RU4 + j];
            fma8(acc, ww.x, q0);
            fma8(acc, ww.y, q1);
            fma8(acc, ww.z, q2);
            fma8(acc, ww.w, q3);
        }
        for (; i < e; i++) {
            fma8(acc, __ldcs(&g_eval[i]), X[__ldcs(&g_ecol[i]) * RU4 + j]);
        }

        float sc0, sc1, sf0, sf1, rs = 0.f;
        if (AFFX || AFFZ1) {
            sc0 = g_scale[2 * j]; sc1 = g_scale[2 * j + 1];
            sf0 = g_shift[2 * j]; sf1 = g_shift[2 * j + 1];
        }
        if (AFFX || HASP) rs = g_rowsum[v];

        if (AFFX) {
#pragma unroll
            for (int b = 0; b < 4; b++) {
                r[b]     = coef * (sc0 * acc[b]     + sf0 * rs);
                r[4 + b] = coef * (sc1 * acc[4 + b] + sf1 * rs);
            }
        } else {
#pragma unroll
            for (int t = 0; t < 8; t++) r[t] = coef * acc[t];
        }
        if (HASZ1) {
            float z[8];
            unpack8(z, __ldcs(&Z1[v * RU4 + j]));
            if (AFFZ1) {
#pragma unroll
                for (int b = 0; b < 4; b++) {
                    r[b]     += s1 * (sc0 * z[b]     + sf0);
                    r[4 + b] += s1 * (sc1 * z[4 + b] + sf1);
                }
            } else {
#pragma unroll
                for (int t = 0; t < 8; t++) r[t] += s1 * z[t];
            }
        }
        if (HASZ2) {
            float z[8];
            unpack8(z, __ldcs(&Z2[v * RU4 + j]));
#pragma unroll
            for (int t = 0; t < 8; t++) r[t] += s2 * z[t];
        }
        if (HASQ) {
            float q0 = qv[2 * j], q1 = qv[2 * j + 1];
#pragma unroll
            for (int b = 0; b < 4; b++) { r[b] += q0; r[4 + b] += q1; }
        }
        if (HASP) {
            float p0 = pv[2 * j], p1 = pv[2 * j + 1];
#pragma unroll
            for (int b = 0; b < 4; b++) { r[b] += rs * p0; r[4 + b] += rs * p1; }
        }
        if (!FINAL) {
            __stcs(&Y[v * RU4 + j], pack8(r));
        }
    }

    if (FINAL) {
        // RU4 == 16, VPB == 16. r covers ch {2j, 2j+1} x b{0..3}
        __shared__ float tile[16 * 32 * 4];
        if (v < VN) {
            float xr[8];
            unpack8(xr, xn[v * 16 + j]);
            float b0 = bias[2 * j], b1 = bias[2 * j + 1];
#pragma unroll
            for (int b = 0; b < 4; b++) {
                r[b]     = fmaxf(r[b]     + b0 + xr[b],     0.f);
                r[4 + b] = fmaxf(r[4 + b] + b1 + xr[4 + b], 0.f);
            }
        } else {
#pragma unroll
            for (int t = 0; t < 8; t++) r[t] = 0.f;
        }
#pragma unroll
        for (int b = 0; b < 4; b++) {
            tile[(vs * 32 + 2 * j) * 4 + b]     = r[b];
            tile[(vs * 32 + 2 * j + 1) * 4 + b] = r[4 + b];
        }
        __syncthreads();
        int vl = threadIdx.x & 15;
        int cw = threadIdx.x >> 4;
        int vv = blockIdx.x * 16 + vl;
        if (vv < VN) {
#pragma unroll
            for (int ci = 0; ci < 2; ci++) {
                int c = cw + ci * 16;
#pragma unroll
                for (int b = 0; b < 4; b++) {
                    outF[(b * 32 + c) * VN + vv] = tile[(vl * 32 + c) * 4 + b];
                }
            }
        }
    }
}

// ---------------- combine: R[v,o,:] = relu(bias[o] + sum_kc w[kc,o]*xk[v,kc,:]) fp16 out -----
// Also accumulates BN stats of relu(out) into g_red.
template<int C, int O, int ITER>
__global__ void __launch_bounds__(256) k_combine(
        const uint4* __restrict__ x0, const uint4* __restrict__ x1,
        const uint4* __restrict__ x2, const uint4* __restrict__ x3,
        const float* __restrict__ w, const float* __restrict__ bias,
        uint2* __restrict__ outR) {
    const int KC = 4 * C;
    const int RU = C / 2;           // uint4 per (v,k) row
    const int VPB = 256 / O;
    extern __shared__ char smem[];
    float* sW = (float*)smem;                                     // KC*O floats
    uint4* sX = (uint4*)(smem + (size_t)KC * O * sizeof(float));  // VPB*4*RU
    __shared__ float sS1[64], sS2[64];
    const int tid = threadIdx.x;

    if (tid < O) { sS1[tid] = 0.f; sS2[tid] = 0.f; }
    for (int i = tid; i < KC * O; i += 256) sW[i] = w[i];

    const int o = tid % O;
    const int vs = tid / O;
    const float bb = bias[o];
    float ls1 = 0.f, ls2 = 0.f;

    for (int it = 0; it < ITER; it++) {
        const int v0 = (blockIdx.x * ITER + it) * VPB;
        __syncthreads();
        for (int i = tid; i < VPB * 4 * RU; i += 256) {
            int vsl = i / (4 * RU);
            int rem = i - vsl * (4 * RU);
            int k = rem / RU, u = rem - k * RU;
            int v = v0 + vsl;
            const uint4* src = (k == 0) ? x0 : (k == 1) ? x1 : (k == 2) ? x2 : x3;
            sX[i] = (v < VN) ? src[v * RU + u] : make_uint4(0u, 0u, 0u, 0u);
        }
        __syncthreads();

        int v = v0 + vs;
        if (v < VN) {
            float4 acc = make_float4(bb, bb, bb, bb);
            const half2* xh = (const half2*)(sX + vs * 4 * RU);
#pragma unroll 8
            for (int kc = 0; kc < KC; kc++) {
                float wv = sW[kc * O + o];
                float2 a = __half22float2(xh[2 * kc]);
                float2 b = __half22float2(xh[2 * kc + 1]);
                acc.x += wv * a.x; acc.y += wv * a.y;
                acc.z += wv * b.x; acc.w += wv * b.y;
            }
            float a = fmaxf(acc.x, 0.f), b = fmaxf(acc.y, 0.f);
            float d = fmaxf(acc.z, 0.f), f = fmaxf(acc.w, 0.f);
            uint2 q;
            half2* h = (half2*)&q;
            h[0] = __floats2half2_rn(a, b);
            h[1] = __floats2half2_rn(d, f);
            outR[v * O + o] = q;
            ls1 += a + b + d + f;
            ls2 += a * a + b * b + d * d + f * f;
        }
    }

    atomicAdd(&sS1[o], ls1);
    atomicAdd(&sS2[o], ls2);
    __syncthreads();
    if (tid < O) {
        atomicAdd(&g_red[tid], sS1[tid]);
        atomicAdd(&g_red[64 + tid], sS2[tid]);
    }
}

// ---------------- combine4 (layer 2): y^_k[v,o,:] = sum_c wf2[k,c,o]*R1[v,c,:]  fp16 ---------
template<int ITER>
__global__ void __launch_bounds__(256) k_combine4(
        const uint4* __restrict__ x, const float* __restrict__ w,
        uint2* __restrict__ y0, uint2* __restrict__ y1,
        uint2* __restrict__ y2, uint2* __restrict__ y3) {
    __shared__ float sW[4 * 64 * 32];   // 32KB
    __shared__ uint4 sX[2 * 32];
    const int tid = threadIdx.x;

    for (int i = tid; i < 4 * 64 * 32; i += 256) sW[i] = w[i];

    const int o2 = tid & 127;
    const int k  = o2 >> 5;
    const int o  = o2 & 31;
    const int vs = tid >> 7;
    uint2* yk = (k == 0) ? y0 : (k == 1) ? y1 : (k == 2) ? y2 : y3;
    const float* wk = sW + k * 64 * 32;

    for (int it = 0; it < ITER; it++) {
        const int v0 = (blockIdx.x * ITER + it) * 2;
        __syncthreads();
        for (int i = tid; i < 2 * 32; i += 256) {
            int vsl = i >> 5, u = i & 31;
            int v = v0 + vsl;
            sX[i] = (v < VN) ? x[v * 32 + u] : make_uint4(0u, 0u, 0u, 0u);
        }
        __syncthreads();

        int v = v0 + vs;
        if (v < VN) {
            float4 acc = make_float4(0.f, 0.f, 0.f, 0.f);
            const half2* xh = (const half2*)(sX + vs * 32);
#pragma unroll 8
            for (int c = 0; c < 64; c++) {
                float wv = wk[c * 32 + o];
                float2 a = __half22float2(xh[2 * c]);
                float2 b = __half22float2(xh[2 * c + 1]);
                acc.x += wv * a.x; acc.y += wv * a.y;
                acc.z += wv * b.x; acc.w += wv * b.y;
            }
            uint2 q;
            half2* h = (half2*)&q;
            h[0] = __floats2half2_rn(acc.x, acc.y);
            h[1] = __floats2half2_rn(acc.z, acc.w);
            yk[v * 32 + o] = q;
        }
    }
}

// ---------------- host orchestration ----------------
extern "C" void kernel_launch(void* const* d_in, const int* in_sizes, int n_in,
                              void* d_out, int out_size) {
    const float* x       = (const float*)d_in[0];
    const int*   ei      = (const int*)  d_in[1];
    const float* vals    = (const float*)d_in[2];
    const float* in_bn_g = (const float*)d_in[3];
    const float* in_bn_b = (const float*)d_in[4];
    const float* in_w    = (const float*)d_in[5];
    const float* in_b    = (const float*)d_in[6];
    const float* h0_bn_g = (const float*)d_in[7];
    const float* h0_bn_b = (const float*)d_in[8];
    const float* h0_w    = (const float*)d_in[9];
    const float* h0_b    = (const float*)d_in[10];
    const float* h1_bn_g = (const float*)d_in[11];
    const float* h1_bn_b = (const float*)d_in[12];
    const float* h1_w    = (const float*)d_in[13];
    const float* h1_b    = (const float*)d_in[14];
    float* out = (float*)d_out;

    const int* rows = ei;
    const int* cols = ei + EN;

    void *pXN, *pR1, *pSA, *pSB, *pSC, *pR0, *pWF, *pBF, *pWF2, *pQB2, *pPB2, *pQB1, *pQO;
    cudaGetSymbolAddress(&pXN, g_XN);
    cudaGetSymbolAddress(&pR1, g_R1);
    cudaGetSymbolAddress(&pSA, g_SA);
    cudaGetSymbolAddress(&pSB, g_SB);
    cudaGetSymbolAddress(&pSC, g_SC);
    cudaGetSymbolAddress(&pR0, g_R0);
    cudaGetSymbolAddress(&pWF, g_wf);
    cudaGetSymbolAddress(&pBF, g_bf);
    cudaGetSymbolAddress(&pWF2, g_wf2);
    cudaGetSymbolAddress(&pQB2, g_qb2);
    cudaGetSymbolAddress(&pPB2, g_pb2);
    cudaGetSymbolAddress(&pQB1, g_qb1);
    cudaGetSymbolAddress(&pQO,  g_qout);
    uint4* XN = (uint4*)pXN;
    uint4* R1 = (uint4*)pR1;
    uint4* SA = (uint4*)pSA;
    uint4* SB = (uint4*)pSB;
    uint4* SC = (uint4*)pSC;
    uint4* R0 = (uint4*)pR0;
    const float* WF  = (const float*)pWF;
    const float* BF  = (const float*)pBF;
    const float* WF2 = (const float*)pWF2;
    const float* QB2 = (const float*)pQB2;
    const float* PB2 = (const float*)pPB2;
    const float* QB1 = (const float*)pQB1;
    const float* QO  = (const float*)pQO;

    cudaFuncSetAttribute(k_combine<32, 64, 4>, cudaFuncAttributeMaxDynamicSharedMemorySize, 36864);
    cudaFuncSetAttribute(k_combine<64, 64, 4>, cudaFuncAttributeMaxDynamicSharedMemorySize, 73728);

    const int gE   = (EN + 255) / 256;
    const int gG32 = (VN + 15) / 16;   // RU4=16 gather grid
    const int gG64 = (VN + 7) / 8;     // RU4=32 gather grid
    const int gCMB = (VN + 15) / 16;

    // ---- CSR build (+ row sums) ----
    k_deg_zero<<<(VN + 255) / 256, 256>>>();
    k_hist<<<gE, 256>>>(rows);
    k_bsum<<<NB_SCAN, 1024>>>();
    k_bscan<<<1, 128>>>();
    k_scan_final<<<NB_SCAN, 1024>>>();
    k_fill<<<gE, 256>>>(rows, cols, vals);

    // ---- input BN ----
    k_stats_in<<<dim3(64, 32), 256>>>(x, 32);
    k_finalize<<<1, 128>>>(in_bn_g, in_bn_b, 32);
    k_apply_in<<<(VN + 63) / 64, 256>>>(x, (uint2*)pXN);

    // ---- layer 0: C=32 -> O=64 (XN is true x0) ----
    k_gather<16,0,0,0,0,0,0,0><<<gG32, 256>>>(1.f, XN, nullptr, 0.f, nullptr, 0.f, SA, nullptr, nullptr, nullptr, nullptr, nullptr);
    k_gather<16,0,1,0,0,0,0,0><<<gG32, 256>>>(2.f, SA, XN, -1.f, nullptr, 0.f, SB, nullptr, nullptr, nullptr, nullptr, nullptr);
    k_gather<16,0,1,0,0,0,0,0><<<gG32, 256>>>(2.f, SB, SA, -1.f, nullptr, 0.f, SC, nullptr, nullptr, nullptr, nullptr, nullptr);
    k_combine<32, 64, 4><<<gCMB, 256, 36864>>>(XN, SA, SB, SC, in_w, in_b, (uint2*)pR0);  // R0 = relu(H0)

    // ---- hidden-0 BN folded ----
    k_finalize<<<1, 128>>>(h0_bn_g, h0_bn_b, 64);
    k_fold1<<<64, 256>>>(h0_w, h0_b);

    // ---- layer 1: C=64 -> O=64; x0 = affine(R0) applied on the fly ----
    k_gather<32,1,0,0,0,0,0,0><<<gG64, 256>>>(1.f, R0, nullptr, 0.f, nullptr, 0.f, SA, nullptr, nullptr, nullptr, nullptr, nullptr);          // x1 = L x0
    k_gather<32,0,1,1,0,0,0,0><<<gG64, 256>>>(2.f, SA, R0, -1.f, nullptr, 0.f, SB, nullptr, nullptr, nullptr, nullptr, nullptr);              // x2 = 2 L x1 - x0
    k_gather<32,0,1,0,0,0,0,0><<<gG64, 256>>>(2.f, SB, SA, -1.f, nullptr, 0.f, SC, nullptr, nullptr, nullptr, nullptr, nullptr);              // x3 = 2 L x2 - x1
    k_combine<64, 64, 4><<<gCMB, 256, 73728>>>(R0, SA, SB, SC, WF, BF, (uint2*)pR1);  // R1 = relu(H1), x0 via folded W

    // ---- hidden-1 BN folded ----
    k_finalize<<<1, 128>>>(h1_bn_g, h1_bn_b, 64);
    k_fold2<<<32, 256>>>(h1_w);

    // ---- layer 2 via Clenshaw on folded y^_k ----
    k_combine4<8><<<(VN + 15) / 16, 256>>>(R1, WF2, (uint2*)pSA, (uint2*)pSB, (uint2*)pSC, (uint2*)pR0);  // y^0..3
    // b2 = 2 L y^3 + y^2 + rs*(2u3) + u2   -> R1 (dead)
    k_gather<16,0,1,0,0,1,1,0><<<gG32, 256>>>(2.f, R0, SC, 1.f, nullptr, 0.f, R1, QB2, PB2, nullptr, nullptr, nullptr);
    // b1 = 2 L b2 + y^1 - y^3 + (u1-u3)    -> SC
    k_gather<16,0,1,0,1,0,1,0><<<gG32, 256>>>(2.f, R1, SB, 1.f, R0, -1.f, SC, QB1, nullptr, nullptr, nullptr, nullptr);
    // out = relu(L b1 + y^0 - b2 + u0 + bias + xn), transposed to (B,32,V)
    k_gather<16,0,1,0,1,0,1,1><<<gG32, 256>>>(1.f, SC, SA, 1.f, R1, -1.f, nullptr, QO, nullptr, h1_b, XN, out);
}